// round 11
// baseline (speedup 1.0000x reference)
#include <cuda_runtime.h>
#include <math.h>

#define N_ROWS 48000
#define DIMS   256
#define KCODES 1024
#define GK     64
#define BM     32                   // rows per CTA
#define NB     (N_ROWS / BM)        // 1500 row-blocks
#define CI_N   8                    // col iterations (128 cols each)
#define KC_N   4                    // k chunks (64 k = 4 k16-steps each)
#define DELTA  1.0f                 // rescore margin (~11 sigma of bf16 noise)
#define DECAYF 0.99f
#define OMDF   0.01f
#define EPSF   1e-5f

// ---------------- scratch (static device globals; no runtime alloc) --------
__device__ uint4 g_xfrag[3000 * 512];       // A frags bf16: [rowgrp16][ks][lane] 24.5 MB
__device__ uint2 g_bfrag[128 * 16 * 32];    // B frags bf16: [st][ks][lane] 512 KB
__device__ float g_shape_sum[KCODES * DIMS];
__device__ float g_shape_cnt[KCODES];
__device__ float g_gain_sum[GK];
__device__ float g_gain_cnt[GK];

__global__ void init_kernel() {
    int i = blockIdx.x * blockDim.x + threadIdx.x;
    if (i < KCODES * DIMS) g_shape_sum[i] = 0.f;
    if (i < KCODES)        g_shape_cnt[i] = 0.f;
    if (i < GK)  { g_gain_sum[i] = 0.f; g_gain_cnt[i] = 0.f; }
}

// ---------------- bf16 helpers ----------------
__device__ __forceinline__ unsigned pk_bf16x2(float lo, float hi) {
    unsigned r;
    asm("cvt.rn.bf16x2.f32 %0, %1, %2;" : "=r"(r) : "f"(hi), "f"(lo));
    return r;
}

__device__ __forceinline__ void mma_bf16(float c[4], uint4 a, uint2 b) {
    asm volatile(
        "mma.sync.aligned.m16n8k16.row.col.f32.bf16.bf16.f32 "
        "{%0,%1,%2,%3},{%4,%5,%6,%7},{%8,%9},{%0,%1,%2,%3};"
        : "+f"(c[0]), "+f"(c[1]), "+f"(c[2]), "+f"(c[3])
        : "r"(a.x), "r"(a.y), "r"(a.z), "r"(a.w), "r"(b.x), "r"(b.y));
}

// ---------------- prep: x -> A-fragment layout (bf16, m16n8k16) ------------
// frag f = g*512 + ks*32 + lane; r = g*16 + (lane>>2); k = ks*16 + (lane&3)*2
__global__ __launch_bounds__(256) void prep_x(const float* __restrict__ x) {
    int tid = threadIdx.x;
    #pragma unroll
    for (int i = 0; i < 4; i++) {
        int f = blockIdx.x * 1024 + tid + i * 256;
        int g = f >> 9, ks = (f >> 5) & 15, lane = f & 31;
        int r = g * 16 + (lane >> 2);
        int k = ks * 16 + (lane & 3) * 2;
        const float* p0 = x + (size_t)r * DIMS + k;
        const float* p1 = x + (size_t)(r + 8) * DIMS + k;
        float2 v00 = *(const float2*)(p0);
        float2 v10 = *(const float2*)(p1);
        float2 v01 = *(const float2*)(p0 + 8);
        float2 v11 = *(const float2*)(p1 + 8);
        uint4 o;
        o.x = pk_bf16x2(v00.x, v00.y);
        o.y = pk_bf16x2(v10.x, v10.y);
        o.z = pk_bf16x2(v01.x, v01.y);
        o.w = pk_bf16x2(v11.x, v11.y);
        g_xfrag[f] = o;
    }
}

// ---------------- prep: cb -> B-fragment layout (bf16) ----------------
__global__ __launch_bounds__(256) void prep_cb(const float* __restrict__ cb) {
    int i = blockIdx.x * 256 + threadIdx.x;   // 65536
    int lane = i & 31, ks = (i >> 5) & 15, st = i >> 9;
    int col = st * 8 + (lane >> 2);
    int k = ks * 16 + (lane & 3) * 2;
    float2 v0 = *(const float2*)(cb + (size_t)col * DIMS + k);
    float2 v1 = *(const float2*)(cb + (size_t)col * DIMS + k + 8);
    uint2 o;
    o.x = pk_bf16x2(v0.x, v0.y);
    o.y = pk_bf16x2(v1.x, v1.y);
    g_bfrag[i] = o;
}

// ---------------- top-3 insert with early reject ----------------
__device__ __forceinline__ void ins3(float* tv, int* tix, float v, int j) {
    if (v <= tv[2]) return;                   // common path: 1 compare
    if (v > tv[0]) {
        tv[2]=tv[1]; tix[2]=tix[1]; tv[1]=tv[0]; tix[1]=tix[0];
        tv[0]=v; tix[0]=j;
    } else if (v > tv[1]) {
        tv[2]=tv[1]; tix[2]=tix[1]; tv[1]=v; tix[1]=j;
    } else {
        tv[2]=v; tix[2]=j;
    }
}

// ---------------- main: bf16 MMA coarse + exact fp32 rescore + epilogue ----
__global__ __launch_bounds__(256, 4) void vq_main(
    const float* __restrict__ x,
    const float* __restrict__ cb,
    const float* __restrict__ gcb,
    float* __restrict__ out_q)
{
    extern __shared__ float sm[];
    uint4* sbf4 = (uint4*)sm;                 // 2 x 1024 uint4 (32 KB) B dbl-buf
    float* cvv  = (float*)(sbf4 + 2048);      // 1536 candidate values (6 KB)
    int*   cix  = (int*)(cvv + 1536);         // 1536 candidate indices (6 KB)
    float* gains  = (float*)(cix + 1536);     // 64
    float* bval   = gains + GK;               // 32
    int*   bidx   = (int*)(bval + BM);        // 32
    float* bscale = (float*)(bidx + BM);      // 32

    const int tid = threadIdx.x, blk = blockIdx.x;
    const int lane = tid & 31, wid = tid >> 5;
    const int wr = wid & 1, wc = wid >> 1;    // 2 x 4 warp grid
    const int row0 = blk * BM;

    if (tid < GK) gains[tid] = gcb[tid];

    const uint4* gb4 = (const uint4*)g_bfrag;
    // A fragments for this warp: global, L1/L2-cached, reused 8x (per ci)
    const uint4* afr = g_xfrag + (size_t)(blk * 2 + wr) * 512;

    // stage B chunk 0 (ci=0, kc=0): 1024 uint4, 4/thread
    #pragma unroll
    for (int i = 0; i < 4; i++) {
        int f = tid + i * 256;
        int stl = f >> 6, kspl = (f >> 4) & 3, w = f & 15;
        sbf4[f] = gb4[(stl * 16 + kspl) * 16 + w];
    }

    float tv0[3], tv1[3]; int tx0[3], tx1[3];
    #pragma unroll
    for (int e = 0; e < 3; e++) {
        tv0[e] = -3.4e38f; tv1[e] = -3.4e38f; tx0[e] = 0; tx1[e] = 0;
    }

    float acc[4][4];
    #pragma unroll
    for (int st = 0; st < 4; st++)
        #pragma unroll
        for (int q = 0; q < 4; q++) acc[st][q] = 0.f;

    __syncthreads();

    const int NQ = CI_N * KC_N;               // 32 chunks
    for (int q = 0; q < NQ; q++) {
        int ci = q >> 2, kc = q & 3;
        uint2* sbf = (uint2*)(sbf4 + (q & 1) * 1024);

        // stage next chunk into other buffer (overlaps MMA below)
        if (q + 1 < NQ) {
            int ci1 = (q + 1) >> 2, kc1 = (q + 1) & 3;
            uint4* nb = sbf4 + ((q + 1) & 1) * 1024;
            #pragma unroll
            for (int i = 0; i < 4; i++) {
                int f = tid + i * 256;
                int stl = f >> 6, kspl = (f >> 4) & 3, w = f & 15;
                nb[f] = gb4[((ci1 * 16 + stl) * 16 + kc1 * 4 + kspl) * 16 + w];
            }
        }

        #pragma unroll
        for (int kspl = 0; kspl < 4; kspl++) {
            uint4 A = afr[(kc * 4 + kspl) * 32 + lane];
            #pragma unroll
            for (int st = 0; st < 4; st++) {
                uint2 B = sbf[((wc * 4 + st) * 4 + kspl) * 32 + lane];
                mma_bf16(acc[st], A, B);
            }
        }

        if (kc == 3) {
            // end of ci: harvest top-3 (2 row-slots per thread)
            #pragma unroll
            for (int st = 0; st < 4; st++) {
                int cb0 = ci * 128 + wc * 32 + st * 8 + 2 * (lane & 3);
                ins3(tv0, tx0, acc[st][0], cb0);
                ins3(tv0, tx0, acc[st][1], cb0 + 1);
                ins3(tv1, tx1, acc[st][2], cb0);
                ins3(tv1, tx1, acc[st][3], cb0 + 1);
                acc[st][0] = 0.f; acc[st][1] = 0.f;
                acc[st][2] = 0.f; acc[st][3] = 0.f;
            }
        }
        __syncthreads();
    }

    // merge candidates: 16 slots x 3 entries per row (rows 0..31 local)
    {
        int rA = wr * 16 + (lane >> 2), rB = rA + 8;
        int slot = wc * 4 + (lane & 3);
        #pragma unroll
        for (int e = 0; e < 3; e++) {
            cvv[rA * 48 + slot * 3 + e] = tv0[e];
            cix[rA * 48 + slot * 3 + e] = tx0[e];
            cvv[rB * 48 + slot * 3 + e] = tv1[e];
            cix[rB * 48 + slot * 3 + e] = tx1[e];
        }
    }
    __syncthreads();

    // ---- exact fp32 rescore of in-margin candidates (one thread per row) ----
    if (tid < BM) {
        int row = tid;
        float m = -3.4e38f;
        #pragma unroll 4
        for (int e = 0; e < 48; e++) m = fmaxf(m, cvv[row * 48 + e]);

        float best = -3.4e38f; int bj = 0x7fffffff;
        const float4* xr = (const float4*)(x + (size_t)(row0 + row) * DIMS);
        for (int e = 0; e < 48; e++) {
            float c = cvv[row * 48 + e];
            if (c >= m - DELTA) {
                int j = cix[row * 48 + e];
                const float4* cr = (const float4*)(cb + (size_t)j * DIMS);
                float a0 = 0.f, a1 = 0.f, a2 = 0.f, a3 = 0.f;
                #pragma unroll 8
                for (int i = 0; i < 64; i++) {
                    float4 xv = xr[i], cw = cr[i];
                    a0 = fmaf(xv.x, cw.x, a0);
                    a1 = fmaf(xv.y, cw.y, a1);
                    a2 = fmaf(xv.z, cw.z, a2);
                    a3 = fmaf(xv.w, cw.w, a3);
                }
                float ex = (a0 + a1) + (a2 + a3);
                if (ex > best || (ex == best && j < bj)) { best = ex; bj = j; }
            }
        }
        bval[row] = best; bidx[row] = bj;

        // gain quantization + scalar stats
        float g = logf(fmaxf(best, EPSF));
        float bd = 3.4e38f; int gi = 0;
        #pragma unroll
        for (int qq = 0; qq < GK; qq++) {
            float d = g - gains[qq];
            float d2 = d * d;
            if (d2 < bd) { bd = d2; gi = qq; }
        }
        atomicAdd(&g_gain_sum[gi], g);
        atomicAdd(&g_gain_cnt[gi], 1.f);
        atomicAdd(&g_shape_cnt[bj], 1.f);
        bscale[row] = expf(gains[gi]);
    }
    __syncthreads();

    // ---- epilogue: quantize output + shape_sum scatter ----
    for (int r = 0; r < BM; r++) {
        int k = bidx[r];
        float sc = bscale[r];
        float cvw = cb[(size_t)k * DIMS + tid];
        out_q[(size_t)(row0 + r) * DIMS + tid] = sc * cvw;
        atomicAdd(&g_shape_sum[(size_t)k * DIMS + tid],
                  x[(size_t)(row0 + r) * DIMS + tid]);
    }
}

// ---------------- finalize: EMA updates ----------------
__device__ __forceinline__ float blockSum256(float v, float* red) {
    __syncthreads();
    int lane = threadIdx.x & 31, w = threadIdx.x >> 5;
    #pragma unroll
    for (int o = 16; o; o >>= 1) v += __shfl_xor_sync(0xffffffffu, v, o);
    if (lane == 0) red[w] = v;
    __syncthreads();
    if (w == 0) {
        float t = (lane < 8) ? red[lane] : 0.f;
        #pragma unroll
        for (int o = 4; o; o >>= 1) t += __shfl_xor_sync(0xffffffffu, t, o);
        if (lane == 0) red[0] = t;
    }
    __syncthreads();
    return red[0];
}

__global__ __launch_bounds__(256) void vq_finalize(
    const float* __restrict__ cb,   const float* __restrict__ gcb,
    const float* __restrict__ snum, const float* __restrict__ gnum,
    float* __restrict__ out_shape,  float* __restrict__ out_gain,
    float* __restrict__ out_snum,   float* __restrict__ out_gnum)
{
    __shared__ float red[8];
    int k = blockIdx.x, t = threadIdx.x;

    float s = g_shape_sum[k * DIMS + t];
    float ss = blockSum256(s * s, red);
    float denom = fmaxf(sqrtf(ss), EPSF);
    float upd = cb[k * DIMS + t] * DECAYF + (s / denom) * OMDF;
    float nn = blockSum256(upd * upd, red);
    float n2 = fmaxf(sqrtf(nn), 1e-12f);
    out_shape[k * DIMS + t] = upd / n2;

    if (t == 0)
        out_snum[k] = snum[k] * DECAYF + g_shape_cnt[k] * OMDF;

    if (k == 0 && t < GK) {
        float cnt  = g_gain_cnt[t];
        float gnew = g_gain_sum[t] / fmaxf(cnt, EPSF);
        out_gain[t] = gcb[t]  * DECAYF + gnew * OMDF;
        out_gnum[t] = gnum[t] * DECAYF + cnt  * OMDF;
    }
}

// ---------------- launch ----------------
extern "C" void kernel_launch(void* const* d_in, const int* in_sizes, int n_in,
                              void* d_out, int out_size) {
    const float* x    = (const float*)d_in[0];   // (48000, 256)
    const float* cb   = (const float*)d_in[1];   // (1024, 256)
    const float* gcb  = (const float*)d_in[2];   // (64,)
    const float* snum = (const float*)d_in[3];   // (1024,)
    const float* gnum = (const float*)d_in[4];   // (64,)

    float* out       = (float*)d_out;
    float* out_q     = out;                             // 12,288,000
    float* out_shape = out_q + (size_t)N_ROWS * DIMS;   // 262,144
    float* out_gain  = out_shape + KCODES * DIMS;       // 64
    float* out_snum  = out_gain + GK;                   // 1024
    float* out_gnum  = out_snum + KCODES;               // 64

    init_kernel<<<(KCODES * DIMS + 255) / 256, 256>>>();
    prep_x<<<1500, 256>>>(x);
    prep_cb<<<256, 256>>>(cb);

    // smem: B dbl 32768 + cvv 6144 + cix 6144 + misc 768 = 45824 B
    size_t smem = 45824;
    cudaFuncSetAttribute(vq_main, cudaFuncAttributeMaxDynamicSharedMemorySize,
                         (int)smem);
    vq_main<<<NB, 256, smem>>>(x, cb, gcb, out_q);

    vq_finalize<<<KCODES, 256>>>(cb, gcb, snum, gnum,
                                 out_shape, out_gain, out_snum, out_gnum);
}

// round 12
// speedup vs baseline: 1.3800x; 1.3800x over previous
#include <cuda_runtime.h>
#include <math.h>

#define N_ROWS 48000
#define DIMS   256
#define KCODES 1024
#define GK     64
#define NB     (N_ROWS / 64)        // 750 row-blocks
#define CI_N   8                    // col iterations (128 cols each)
#define KC_N   4                    // k chunks (64 k = 4 k16-steps each)
#define DELTA  1.0f                 // rescore margin (~11 sigma of bf16 noise)
#define DECAYF 0.99f
#define OMDF   0.01f
#define EPSF   1e-5f

// ---------------- scratch (static device globals; no runtime alloc) --------
__device__ uint4 g_xfrag[NB * 2048];        // A frags bf16 24.5 MB
__device__ uint2 g_bfrag[128 * 16 * 32];    // B frags bf16 512 KB
__device__ float g_shape_sum[KCODES * DIMS];
__device__ float g_shape_cnt[KCODES];
__device__ float g_gain_sum[GK];
__device__ float g_gain_cnt[GK];

__global__ void init_kernel() {
    int i = blockIdx.x * blockDim.x + threadIdx.x;
    if (i < KCODES * DIMS) g_shape_sum[i] = 0.f;
    if (i < KCODES)        g_shape_cnt[i] = 0.f;
    if (i < GK)  { g_gain_sum[i] = 0.f; g_gain_cnt[i] = 0.f; }
}

// ---------------- bf16 helpers ----------------
__device__ __forceinline__ unsigned pk_bf16x2(float lo, float hi) {
    unsigned r;
    asm("cvt.rn.bf16x2.f32 %0, %1, %2;" : "=r"(r) : "f"(hi), "f"(lo));
    return r;
}

__device__ __forceinline__ void mma_bf16(float c[4], uint4 a, uint2 b) {
    asm volatile(
        "mma.sync.aligned.m16n8k16.row.col.f32.bf16.bf16.f32 "
        "{%0,%1,%2,%3},{%4,%5,%6,%7},{%8,%9},{%0,%1,%2,%3};"
        : "+f"(c[0]), "+f"(c[1]), "+f"(c[2]), "+f"(c[3])
        : "r"(a.x), "r"(a.y), "r"(a.z), "r"(a.w), "r"(b.x), "r"(b.y));
}

// ---------------- prep: x -> A-fragment layout (bf16, m16n8k16) ------------
__global__ __launch_bounds__(256) void prep_x(const float* __restrict__ x) {
    int blk = blockIdx.x, tid = threadIdx.x;
    #pragma unroll
    for (int i = 0; i < 8; i++) {
        int f = tid + i * 256;
        int wr = f >> 9, ks = (f >> 5) & 15, lane = f & 31;
        int r = blk * 64 + wr * 16 + (lane >> 2);
        int k = ks * 16 + (lane & 3) * 2;
        const float* p0 = x + (size_t)r * DIMS + k;
        const float* p1 = x + (size_t)(r + 8) * DIMS + k;
        float2 v00 = *(const float2*)(p0);
        float2 v10 = *(const float2*)(p1);
        float2 v01 = *(const float2*)(p0 + 8);
        float2 v11 = *(const float2*)(p1 + 8);
        uint4 o;
        o.x = pk_bf16x2(v00.x, v00.y);
        o.y = pk_bf16x2(v10.x, v10.y);
        o.z = pk_bf16x2(v01.x, v01.y);
        o.w = pk_bf16x2(v11.x, v11.y);
        g_xfrag[blk * 2048 + f] = o;
    }
}

// ---------------- prep: cb -> B-fragment layout (bf16) ----------------
__global__ __launch_bounds__(256) void prep_cb(const float* __restrict__ cb) {
    int i = blockIdx.x * 256 + threadIdx.x;   // 65536
    int lane = i & 31, ks = (i >> 5) & 15, st = i >> 9;
    int col = st * 8 + (lane >> 2);
    int k = ks * 16 + (lane & 3) * 2;
    float2 v0 = *(const float2*)(cb + (size_t)col * DIMS + k);
    float2 v1 = *(const float2*)(cb + (size_t)col * DIMS + k + 8);
    uint2 o;
    o.x = pk_bf16x2(v0.x, v0.y);
    o.y = pk_bf16x2(v1.x, v1.y);
    g_bfrag[i] = o;
}

// ---------------- top-4 insert with early reject ----------------
__device__ __forceinline__ void ins4(float* tv, int* tix, float v, int j) {
    if (v <= tv[3]) return;                   // common path: 1 compare
    if (v > tv[0]) {
        tv[3]=tv[2]; tix[3]=tix[2]; tv[2]=tv[1]; tix[2]=tix[1];
        tv[1]=tv[0]; tix[1]=tix[0]; tv[0]=v; tix[0]=j;
    } else if (v > tv[1]) {
        tv[3]=tv[2]; tix[3]=tix[2]; tv[2]=tv[1]; tix[2]=tix[1];
        tv[1]=v; tix[1]=j;
    } else if (v > tv[2]) {
        tv[3]=tv[2]; tix[3]=tix[2]; tv[2]=v; tix[2]=j;
    } else {
        tv[3]=v; tix[3]=j;
    }
}

// ---------------- main: bf16 MMA coarse + exact fp32 rescore + epilogue ----
__global__ __launch_bounds__(256, 3) void vq_main(
    const float* __restrict__ x,
    const float* __restrict__ cb,
    const float* __restrict__ gcb,
    float* __restrict__ out_q)
{
    extern __shared__ float sm[];
    uint4* saf  = (uint4*)sm;                 // 2048 uint4 (32 KB) A frags
    uint4* sbf4 = saf + 2048;                 // 1024 uint4 (16 KB) B chunk
    uint2* sbf  = (uint2*)sbf4;
    float* cvv  = (float*)(sbf4 + 1024);      // 2048 candidate values (8 KB)
    int*   cix  = (int*)(cvv + 2048);         // 2048 candidate indices (8 KB)
    float* gains  = (float*)(cix + 2048);     // 64
    float* bval   = gains + GK;               // 64
    int*   bidx   = (int*)(bval + 64);        // 64
    float* bscale = (float*)(bidx + 64);      // 64

    const int tid = threadIdx.x, blk = blockIdx.x;
    const int lane = tid & 31, wid = tid >> 5;
    const int wr = wid & 3, wc = wid >> 2;
    const int row0 = blk * 64;

    // stage A fragments (32 KB, coalesced)
    #pragma unroll
    for (int i = 0; i < 8; i++)
        saf[tid + i * 256] = g_xfrag[blk * 2048 + tid + i * 256];
    if (tid < GK) gains[tid] = gcb[tid];

    float tv0[4], tv1[4]; int tx0[4], tx1[4];
    #pragma unroll
    for (int e = 0; e < 4; e++) {
        tv0[e] = -3.4e38f; tv1[e] = -3.4e38f; tx0[e] = 0; tx1[e] = 0;
    }

    const uint4* gb4 = (const uint4*)g_bfrag;

    for (int ci = 0; ci < CI_N; ci++) {
        float acc[8][4];
        #pragma unroll
        for (int st = 0; st < 8; st++)
            #pragma unroll
            for (int q = 0; q < 4; q++) acc[st][q] = 0.f;

        for (int kc = 0; kc < KC_N; kc++) {
            __syncthreads();
            // stage B frags for (ci, kc): 1024 uint4, 4 per thread
            #pragma unroll
            for (int i = 0; i < 4; i++) {
                int f = tid + i * 256;
                int stl = f >> 6, kspl = (f >> 4) & 3, w = f & 15;
                sbf4[f] = gb4[((ci * 16 + stl) * 16 + kc * 4 + kspl) * 16 + w];
            }
            __syncthreads();

            #pragma unroll
            for (int kspl = 0; kspl < 4; kspl++) {
                uint4 A = saf[wr * 512 + (kc * 4 + kspl) * 32 + lane];
                #pragma unroll
                for (int st = 0; st < 8; st++) {
                    uint2 B = sbf[((wc * 8 + st) * 4 + kspl) * 32 + lane];
                    mma_bf16(acc[st], A, B);
                }
            }
        }

        // coarse top-4 update (2 row-slots per thread)
        #pragma unroll
        for (int st = 0; st < 8; st++) {
            int cb0 = ci * 128 + wc * 64 + st * 8 + 2 * (lane & 3);
            ins4(tv0, tx0, acc[st][0], cb0);
            ins4(tv0, tx0, acc[st][1], cb0 + 1);
            ins4(tv1, tx1, acc[st][2], cb0);
            ins4(tv1, tx1, acc[st][3], cb0 + 1);
        }
    }

    // merge candidates to smem: 8 slots x 4 entries per row
    {
        int rA = wr * 16 + (lane >> 2), rB = rA + 8;
        int slot = wc * 4 + (lane & 3);
        #pragma unroll
        for (int e = 0; e < 4; e++) {
            cvv[rA * 32 + slot * 4 + e] = tv0[e];
            cix[rA * 32 + slot * 4 + e] = tx0[e];
            cvv[rB * 32 + slot * 4 + e] = tv1[e];
            cix[rB * 32 + slot * 4 + e] = tx1[e];
        }
    }
    __syncthreads();

    // ---- exact fp32 rescore: 4 threads per row (sub-lanes), shfl merge ----
    {
        int row = tid >> 2;          // 0..63
        int sub = tid & 3;           // 0..3  (lanes row*4+sub share a warp)

        // margin max over this sub's 8 entries, then merge across 4 subs
        float m = -3.4e38f;
        #pragma unroll
        for (int e = 0; e < 8; e++)
            m = fmaxf(m, cvv[row * 32 + sub * 8 + e]);
        m = fmaxf(m, __shfl_xor_sync(0xffffffffu, m, 1));
        m = fmaxf(m, __shfl_xor_sync(0xffffffffu, m, 2));

        // exact rescore of in-margin entries in this sub
        float best = -3.4e38f; int bj = 0x7fffffff;
        const float4* xr = (const float4*)(x + (size_t)(row0 + row) * DIMS);
        #pragma unroll
        for (int e = 0; e < 8; e++) {
            float c = cvv[row * 32 + sub * 8 + e];
            if (c >= m - DELTA) {
                int j = cix[row * 32 + sub * 8 + e];
                const float4* cr = (const float4*)(cb + (size_t)j * DIMS);
                float a0 = 0.f, a1 = 0.f, a2 = 0.f, a3 = 0.f;
                #pragma unroll 8
                for (int i = 0; i < 64; i++) {
                    float4 xv = xr[i], cw = cr[i];
                    a0 = fmaf(xv.x, cw.x, a0);
                    a1 = fmaf(xv.y, cw.y, a1);
                    a2 = fmaf(xv.z, cw.z, a2);
                    a3 = fmaf(xv.w, cw.w, a3);
                }
                float ex = (a0 + a1) + (a2 + a3);
                if (ex > best || (ex == best && j < bj)) { best = ex; bj = j; }
            }
        }
        // merge (best, bj) across the 4 sub-lanes with index tie-break
        #pragma unroll
        for (int off = 1; off < 4; off <<= 1) {
            float ov = __shfl_xor_sync(0xffffffffu, best, off);
            int   oj = __shfl_xor_sync(0xffffffffu, bj, off);
            if (ov > best || (ov == best && oj < bj)) { best = ov; bj = oj; }
        }

        if (sub == 0) {
            bval[row] = best; bidx[row] = bj;
            // gain quantization + scalar stats
            float g = logf(fmaxf(best, EPSF));
            float bd = 3.4e38f; int gi = 0;
            #pragma unroll
            for (int qq = 0; qq < GK; qq++) {
                float d = g - gains[qq];
                float d2 = d * d;
                if (d2 < bd) { bd = d2; gi = qq; }
            }
            atomicAdd(&g_gain_sum[gi], g);
            atomicAdd(&g_gain_cnt[gi], 1.f);
            atomicAdd(&g_shape_cnt[bj], 1.f);
            bscale[row] = expf(gains[gi]);
        }
    }
    __syncthreads();

    // ---- epilogue: quantize output + shape_sum scatter (float4) ----
    {
        int rr = tid >> 6;               // 0..3
        int d4 = (tid & 63) * 4;         // dim offset
        #pragma unroll 4
        for (int it = 0; it < 16; it++) {
            int r = it * 4 + rr;
            int k = bidx[r];
            float sc = bscale[r];
            float4 cvw = *(const float4*)(cb + (size_t)k * DIMS + d4);
            float4 xv  = *(const float4*)(x + (size_t)(row0 + r) * DIMS + d4);
            float4 o;
            o.x = sc * cvw.x; o.y = sc * cvw.y;
            o.z = sc * cvw.z; o.w = sc * cvw.w;
            *(float4*)(out_q + (size_t)(row0 + r) * DIMS + d4) = o;
            float* ss = &g_shape_sum[(size_t)k * DIMS + d4];
            atomicAdd(ss + 0, xv.x);
            atomicAdd(ss + 1, xv.y);
            atomicAdd(ss + 2, xv.z);
            atomicAdd(ss + 3, xv.w);
        }
    }
}

// ---------------- finalize: EMA updates ----------------
__device__ __forceinline__ float blockSum256(float v, float* red) {
    __syncthreads();
    int lane = threadIdx.x & 31, w = threadIdx.x >> 5;
    #pragma unroll
    for (int o = 16; o; o >>= 1) v += __shfl_xor_sync(0xffffffffu, v, o);
    if (lane == 0) red[w] = v;
    __syncthreads();
    if (w == 0) {
        float t = (lane < 8) ? red[lane] : 0.f;
        #pragma unroll
        for (int o = 4; o; o >>= 1) t += __shfl_xor_sync(0xffffffffu, t, o);
        if (lane == 0) red[0] = t;
    }
    __syncthreads();
    return red[0];
}

__global__ __launch_bounds__(256) void vq_finalize(
    const float* __restrict__ cb,   const float* __restrict__ gcb,
    const float* __restrict__ snum, const float* __restrict__ gnum,
    float* __restrict__ out_shape,  float* __restrict__ out_gain,
    float* __restrict__ out_snum,   float* __restrict__ out_gnum)
{
    __shared__ float red[8];
    int k = blockIdx.x, t = threadIdx.x;

    float s = g_shape_sum[k * DIMS + t];
    float ss = blockSum256(s * s, red);
    float denom = fmaxf(sqrtf(ss), EPSF);
    float upd = cb[k * DIMS + t] * DECAYF + (s / denom) * OMDF;
    float nn = blockSum256(upd * upd, red);
    float n2 = fmaxf(sqrtf(nn), 1e-12f);
    out_shape[k * DIMS + t] = upd / n2;

    if (t == 0)
        out_snum[k] = snum[k] * DECAYF + g_shape_cnt[k] * OMDF;

    if (k == 0 && t < GK) {
        float cnt  = g_gain_cnt[t];
        float gnew = g_gain_sum[t] / fmaxf(cnt, EPSF);
        out_gain[t] = gcb[t]  * DECAYF + gnew * OMDF;
        out_gnum[t] = gnum[t] * DECAYF + cnt  * OMDF;
    }
}

// ---------------- launch ----------------
extern "C" void kernel_launch(void* const* d_in, const int* in_sizes, int n_in,
                              void* d_out, int out_size) {
    const float* x    = (const float*)d_in[0];   // (48000, 256)
    const float* cb   = (const float*)d_in[1];   // (1024, 256)
    const float* gcb  = (const float*)d_in[2];   // (64,)
    const float* snum = (const float*)d_in[3];   // (1024,)
    const float* gnum = (const float*)d_in[4];   // (64,)

    float* out       = (float*)d_out;
    float* out_q     = out;                             // 12,288,000
    float* out_shape = out_q + (size_t)N_ROWS * DIMS;   // 262,144
    float* out_gain  = out_shape + KCODES * DIMS;       // 64
    float* out_snum  = out_gain + GK;                   // 1024
    float* out_gnum  = out_snum + KCODES;               // 64

    init_kernel<<<(KCODES * DIMS + 255) / 256, 256>>>();
    prep_x<<<NB, 256>>>(x);
    prep_cb<<<256, 256>>>(cb);

    // smem: A 32768 + B 16384 + cvv 8192 + cix 8192 + misc 1024 = 66560 B
    size_t smem = 66560;
    cudaFuncSetAttribute(vq_main, cudaFuncAttributeMaxDynamicSharedMemorySize,
                         (int)smem);
    vq_main<<<NB, 256, smem>>>(x, cb, gcb, out_q);

    vq_finalize<<<KCODES, 256>>>(cb, gcb, snum, gnum,
                                 out_shape, out_gain, out_snum, out_gnum);
}

// round 13
// speedup vs baseline: 1.4717x; 1.0665x over previous
#include <cuda_runtime.h>
#include <math.h>

#define N_ROWS 48000
#define DIMS   256
#define KCODES 1024
#define GK     64
#define NB     (N_ROWS / 64)        // 750 row-blocks
#define CI_N   8                    // col iterations (128 cols each)
#define KC_N   4                    // k chunks (64 k = 4 k16-steps each)
#define DELTA  1.0f                 // rescore margin (~11 sigma of bf16 noise)
#define DECAYF 0.99f
#define OMDF   0.01f
#define EPSF   1e-5f

// ---------------- scratch (static device globals; no runtime alloc) --------
__device__ uint4 g_xfrag[NB * 2048];        // A frags bf16 24.5 MB
__device__ uint2 g_bfrag[128 * 16 * 32];    // B frags bf16 512 KB
__device__ float g_shape_sum[KCODES * DIMS];
__device__ float g_shape_cnt[KCODES];
__device__ float g_gain_sum[GK];
__device__ float g_gain_cnt[GK];

__global__ void init_kernel() {
    int i = blockIdx.x * blockDim.x + threadIdx.x;
    if (i < KCODES * DIMS) g_shape_sum[i] = 0.f;
    if (i < KCODES)        g_shape_cnt[i] = 0.f;
    if (i < GK)  { g_gain_sum[i] = 0.f; g_gain_cnt[i] = 0.f; }
}

// ---------------- bf16 helpers ----------------
__device__ __forceinline__ unsigned pk_bf16x2(float lo, float hi) {
    unsigned r;
    asm("cvt.rn.bf16x2.f32 %0, %1, %2;" : "=r"(r) : "f"(hi), "f"(lo));
    return r;
}

__device__ __forceinline__ void mma_bf16(float c[4], uint4 a, uint2 b) {
    asm volatile(
        "mma.sync.aligned.m16n8k16.row.col.f32.bf16.bf16.f32 "
        "{%0,%1,%2,%3},{%4,%5,%6,%7},{%8,%9},{%0,%1,%2,%3};"
        : "+f"(c[0]), "+f"(c[1]), "+f"(c[2]), "+f"(c[3])
        : "r"(a.x), "r"(a.y), "r"(a.z), "r"(a.w), "r"(b.x), "r"(b.y));
}

// ---------------- prep: x -> A-fragment layout (bf16, m16n8k16) ------------
__global__ __launch_bounds__(256) void prep_x(const float* __restrict__ x) {
    int blk = blockIdx.x, tid = threadIdx.x;
    #pragma unroll
    for (int i = 0; i < 8; i++) {
        int f = tid + i * 256;
        int wr = f >> 9, ks = (f >> 5) & 15, lane = f & 31;
        int r = blk * 64 + wr * 16 + (lane >> 2);
        int k = ks * 16 + (lane & 3) * 2;
        const float* p0 = x + (size_t)r * DIMS + k;
        const float* p1 = x + (size_t)(r + 8) * DIMS + k;
        float2 v00 = *(const float2*)(p0);
        float2 v10 = *(const float2*)(p1);
        float2 v01 = *(const float2*)(p0 + 8);
        float2 v11 = *(const float2*)(p1 + 8);
        uint4 o;
        o.x = pk_bf16x2(v00.x, v00.y);
        o.y = pk_bf16x2(v10.x, v10.y);
        o.z = pk_bf16x2(v01.x, v01.y);
        o.w = pk_bf16x2(v11.x, v11.y);
        g_xfrag[blk * 2048 + f] = o;
    }
}

// ---------------- prep: cb -> B-fragment layout (bf16) ----------------
__global__ __launch_bounds__(256) void prep_cb(const float* __restrict__ cb) {
    int i = blockIdx.x * 256 + threadIdx.x;   // 65536
    int lane = i & 31, ks = (i >> 5) & 15, st = i >> 9;
    int col = st * 8 + (lane >> 2);
    int k = ks * 16 + (lane & 3) * 2;
    float2 v0 = *(const float2*)(cb + (size_t)col * DIMS + k);
    float2 v1 = *(const float2*)(cb + (size_t)col * DIMS + k + 8);
    uint2 o;
    o.x = pk_bf16x2(v0.x, v0.y);
    o.y = pk_bf16x2(v1.x, v1.y);
    g_bfrag[i] = o;
}

// ---------------- top-4 insert with early reject ----------------
__device__ __forceinline__ void ins4(float* tv, int* tix, float v, int j) {
    if (v <= tv[3]) return;                   // common path: 1 compare
    if (v > tv[0]) {
        tv[3]=tv[2]; tix[3]=tix[2]; tv[2]=tv[1]; tix[2]=tix[1];
        tv[1]=tv[0]; tix[1]=tix[0]; tv[0]=v; tix[0]=j;
    } else if (v > tv[1]) {
        tv[3]=tv[2]; tix[3]=tix[2]; tv[2]=tv[1]; tix[2]=tix[1];
        tv[1]=v; tix[1]=j;
    } else if (v > tv[2]) {
        tv[3]=tv[2]; tix[3]=tix[2]; tv[2]=v; tix[2]=j;
    } else {
        tv[3]=v; tix[3]=j;
    }
}

// ---------------- main: bf16 MMA coarse + exact fp32 rescore + epilogue ----
__global__ __launch_bounds__(256, 2) void vq_main(
    const float* __restrict__ x,
    const float* __restrict__ cb,
    const float* __restrict__ gcb,
    float* __restrict__ out_q)
{
    extern __shared__ float sm[];
    uint4* saf  = (uint4*)sm;                 // 2048 uint4 (32 KB) A frags
    uint4* sbf4 = saf + 2048;                 // 2 x 1024 uint4 (32 KB) B dbl-buf
    float* cvv  = (float*)(sbf4 + 2048);      // 2048 candidate values (8 KB)
    int*   cix  = (int*)(cvv + 2048);         // 2048 candidate indices (8 KB)
    float* gains  = (float*)(cix + 2048);     // 64
    float* bval   = gains + GK;               // 64
    int*   bidx   = (int*)(bval + 64);        // 64
    float* bscale = (float*)(bidx + 64);      // 64

    const int tid = threadIdx.x, blk = blockIdx.x;
    const int lane = tid & 31, wid = tid >> 5;
    const int wr = wid & 3, wc = wid >> 2;
    const int row0 = blk * 64;

    // stage A fragments (32 KB, coalesced)
    #pragma unroll
    for (int i = 0; i < 8; i++)
        saf[tid + i * 256] = g_xfrag[blk * 2048 + tid + i * 256];
    if (tid < GK) gains[tid] = gcb[tid];

    const uint4* gb4 = (const uint4*)g_bfrag;

    // stage B chunk 0 (ci=0, kc=0): 1024 uint4, 4/thread
    #pragma unroll
    for (int i = 0; i < 4; i++) {
        int f = tid + i * 256;
        int stl = f >> 6, kspl = (f >> 4) & 3, w = f & 15;
        sbf4[f] = gb4[(stl * 16 + kspl) * 16 + w];
    }

    float tv0[4], tv1[4]; int tx0[4], tx1[4];
    #pragma unroll
    for (int e = 0; e < 4; e++) {
        tv0[e] = -3.4e38f; tv1[e] = -3.4e38f; tx0[e] = 0; tx1[e] = 0;
    }

    float acc[8][4];
    #pragma unroll
    for (int st = 0; st < 8; st++)
        #pragma unroll
        for (int q = 0; q < 4; q++) acc[st][q] = 0.f;

    __syncthreads();

    const int NQ = CI_N * KC_N;               // 32 chunks
    for (int q = 0; q < NQ; q++) {
        int ci = q >> 2, kc = q & 3;
        uint2* sbf = (uint2*)(sbf4 + (q & 1) * 1024);

        // stage next chunk into the other buffer (overlaps MMA below).
        // Safe: buffer (q+1)&1 was last read by compute(q-1), which all
        // warps finished before the barrier at the end of iteration q-1.
        if (q + 1 < NQ) {
            int ci1 = (q + 1) >> 2, kc1 = (q + 1) & 3;
            uint4* nb = sbf4 + ((q + 1) & 1) * 1024;
            #pragma unroll
            for (int i = 0; i < 4; i++) {
                int f = tid + i * 256;
                int stl = f >> 6, kspl = (f >> 4) & 3, w = f & 15;
                nb[f] = gb4[((ci1 * 16 + stl) * 16 + kc1 * 4 + kspl) * 16 + w];
            }
        }

        #pragma unroll
        for (int kspl = 0; kspl < 4; kspl++) {
            uint4 A = saf[wr * 512 + (kc * 4 + kspl) * 32 + lane];
            #pragma unroll
            for (int st = 0; st < 8; st++) {
                uint2 B = sbf[((wc * 8 + st) * 4 + kspl) * 32 + lane];
                mma_bf16(acc[st], A, B);
            }
        }

        if (kc == 3) {
            // end of ci: coarse top-4 harvest (2 row-slots per thread)
            #pragma unroll
            for (int st = 0; st < 8; st++) {
                int cb0 = ci * 128 + wc * 64 + st * 8 + 2 * (lane & 3);
                ins4(tv0, tx0, acc[st][0], cb0);
                ins4(tv0, tx0, acc[st][1], cb0 + 1);
                ins4(tv1, tx1, acc[st][2], cb0);
                ins4(tv1, tx1, acc[st][3], cb0 + 1);
                acc[st][0] = 0.f; acc[st][1] = 0.f;
                acc[st][2] = 0.f; acc[st][3] = 0.f;
            }
        }
        __syncthreads();
    }

    // merge candidates to smem: 8 slots x 4 entries per row
    {
        int rA = wr * 16 + (lane >> 2), rB = rA + 8;
        int slot = wc * 4 + (lane & 3);
        #pragma unroll
        for (int e = 0; e < 4; e++) {
            cvv[rA * 32 + slot * 4 + e] = tv0[e];
            cix[rA * 32 + slot * 4 + e] = tx0[e];
            cvv[rB * 32 + slot * 4 + e] = tv1[e];
            cix[rB * 32 + slot * 4 + e] = tx1[e];
        }
    }
    __syncthreads();

    // ---- exact fp32 rescore: 4 threads per row (sub-lanes), shfl merge ----
    {
        int row = tid >> 2;          // 0..63
        int sub = tid & 3;           // 0..3  (lanes row*4+sub share a warp)

        float m = -3.4e38f;
        #pragma unroll
        for (int e = 0; e < 8; e++)
            m = fmaxf(m, cvv[row * 32 + sub * 8 + e]);
        m = fmaxf(m, __shfl_xor_sync(0xffffffffu, m, 1));
        m = fmaxf(m, __shfl_xor_sync(0xffffffffu, m, 2));

        float best = -3.4e38f; int bj = 0x7fffffff;
        const float4* xr = (const float4*)(x + (size_t)(row0 + row) * DIMS);
        #pragma unroll
        for (int e = 0; e < 8; e++) {
            float c = cvv[row * 32 + sub * 8 + e];
            if (c >= m - DELTA) {
                int j = cix[row * 32 + sub * 8 + e];
                const float4* cr = (const float4*)(cb + (size_t)j * DIMS);
                float a0 = 0.f, a1 = 0.f, a2 = 0.f, a3 = 0.f;
                #pragma unroll 8
                for (int i = 0; i < 64; i++) {
                    float4 xv = xr[i], cw = cr[i];
                    a0 = fmaf(xv.x, cw.x, a0);
                    a1 = fmaf(xv.y, cw.y, a1);
                    a2 = fmaf(xv.z, cw.z, a2);
                    a3 = fmaf(xv.w, cw.w, a3);
                }
                float ex = (a0 + a1) + (a2 + a3);
                if (ex > best || (ex == best && j < bj)) { best = ex; bj = j; }
            }
        }
        #pragma unroll
        for (int off = 1; off < 4; off <<= 1) {
            float ov = __shfl_xor_sync(0xffffffffu, best, off);
            int   oj = __shfl_xor_sync(0xffffffffu, bj, off);
            if (ov > best || (ov == best && oj < bj)) { best = ov; bj = oj; }
        }

        if (sub == 0) {
            bval[row] = best; bidx[row] = bj;
            float g = logf(fmaxf(best, EPSF));
            float bd = 3.4e38f; int gi = 0;
            #pragma unroll
            for (int qq = 0; qq < GK; qq++) {
                float d = g - gains[qq];
                float d2 = d * d;
                if (d2 < bd) { bd = d2; gi = qq; }
            }
            atomicAdd(&g_gain_sum[gi], g);
            atomicAdd(&g_gain_cnt[gi], 1.f);
            atomicAdd(&g_shape_cnt[bj], 1.f);
            bscale[row] = expf(gains[gi]);
        }
    }
    __syncthreads();

    // ---- epilogue: quantize output + shape_sum scatter (float4) ----
    {
        int rr = tid >> 6;               // 0..3
        int d4 = (tid & 63) * 4;         // dim offset
        #pragma unroll 4
        for (int it = 0; it < 16; it++) {
            int r = it * 4 + rr;
            int k = bidx[r];
            float sc = bscale[r];
            float4 cvw = *(const float4*)(cb + (size_t)k * DIMS + d4);
            float4 xv  = *(const float4*)(x + (size_t)(row0 + r) * DIMS + d4);
            float4 o;
            o.x = sc * cvw.x; o.y = sc * cvw.y;
            o.z = sc * cvw.z; o.w = sc * cvw.w;
            *(float4*)(out_q + (size_t)(row0 + r) * DIMS + d4) = o;
            float* ss = &g_shape_sum[(size_t)k * DIMS + d4];
            atomicAdd(ss + 0, xv.x);
            atomicAdd(ss + 1, xv.y);
            atomicAdd(ss + 2, xv.z);
            atomicAdd(ss + 3, xv.w);
        }
    }
}

// ---------------- finalize: EMA updates ----------------
__device__ __forceinline__ float blockSum256(float v, float* red) {
    __syncthreads();
    int lane = threadIdx.x & 31, w = threadIdx.x >> 5;
    #pragma unroll
    for (int o = 16; o; o >>= 1) v += __shfl_xor_sync(0xffffffffu, v, o);
    if (lane == 0) red[w] = v;
    __syncthreads();
    if (w == 0) {
        float t = (lane < 8) ? red[lane] : 0.f;
        #pragma unroll
        for (int o = 4; o; o >>= 1) t += __shfl_xor_sync(0xffffffffu, t, o);
        if (lane == 0) red[0] = t;
    }
    __syncthreads();
    return red[0];
}

__global__ __launch_bounds__(256) void vq_finalize(
    const float* __restrict__ cb,   const float* __restrict__ gcb,
    const float* __restrict__ snum, const float* __restrict__ gnum,
    float* __restrict__ out_shape,  float* __restrict__ out_gain,
    float* __restrict__ out_snum,   float* __restrict__ out_gnum)
{
    __shared__ float red[8];
    int k = blockIdx.x, t = threadIdx.x;

    float s = g_shape_sum[k * DIMS + t];
    float ss = blockSum256(s * s, red);
    float denom = fmaxf(sqrtf(ss), EPSF);
    float upd = cb[k * DIMS + t] * DECAYF + (s / denom) * OMDF;
    float nn = blockSum256(upd * upd, red);
    float n2 = fmaxf(sqrtf(nn), 1e-12f);
    out_shape[k * DIMS + t] = upd / n2;

    if (t == 0)
        out_snum[k] = snum[k] * DECAYF + g_shape_cnt[k] * OMDF;

    if (k == 0 && t < GK) {
        float cnt  = g_gain_cnt[t];
        float gnew = g_gain_sum[t] / fmaxf(cnt, EPSF);
        out_gain[t] = gcb[t]  * DECAYF + gnew * OMDF;
        out_gnum[t] = gnum[t] * DECAYF + cnt  * OMDF;
    }
}

// ---------------- launch ----------------
extern "C" void kernel_launch(void* const* d_in, const int* in_sizes, int n_in,
                              void* d_out, int out_size) {
    const float* x    = (const float*)d_in[0];   // (48000, 256)
    const float* cb   = (const float*)d_in[1];   // (1024, 256)
    const float* gcb  = (const float*)d_in[2];   // (64,)
    const float* snum = (const float*)d_in[3];   // (1024,)
    const float* gnum = (const float*)d_in[4];   // (64,)

    float* out       = (float*)d_out;
    float* out_q     = out;                             // 12,288,000
    float* out_shape = out_q + (size_t)N_ROWS * DIMS;   // 262,144
    float* out_gain  = out_shape + KCODES * DIMS;       // 64
    float* out_snum  = out_gain + GK;                   // 1024
    float* out_gnum  = out_snum + KCODES;               // 64

    init_kernel<<<(KCODES * DIMS + 255) / 256, 256>>>();
    prep_x<<<NB, 256>>>(x);
    prep_cb<<<256, 256>>>(cb);

    // smem: A 32768 + B dbl 32768 + cvv 8192 + cix 8192 + misc 1024 = 82944 B
    size_t smem = 82944;
    cudaFuncSetAttribute(vq_main, cudaFuncAttributeMaxDynamicSharedMemorySize,
                         (int)smem);
    vq_main<<<NB, 256, smem>>>(x, cb, gcb, out_q);

    vq_finalize<<<KCODES, 256>>>(cb, gcb, snum, gnum,
                                 out_shape, out_gain, out_snum, out_gnum);
}

// round 14
// speedup vs baseline: 1.4913x; 1.0133x over previous
#include <cuda_runtime.h>
#include <math.h>

#define N_ROWS 48000
#define DIMS   256
#define KCODES 1024
#define GK     64
#define NB     (N_ROWS / 64)        // 750 row-blocks
#define CI_N   8                    // col iterations (128 cols each)
#define KC_N   4                    // k chunks (64 k each)
#define DELTA  1.0f                 // rescore margin (~11 sigma of bf16 noise)
#define DECAYF 0.99f
#define OMDF   0.01f
#define EPSF   1e-5f

// ---------------- scratch (static device globals; no runtime alloc) --------
__device__ uint4 g_xfrag[NB * 2048];    // A frags bf16 24.5 MB
__device__ uint4 g_bfrag4[32768];       // B frags bf16 paired k32: [st128][kp8][lane32] 512 KB
__device__ float g_shape_sum[KCODES * DIMS];
__device__ float g_shape_cnt[KCODES];
__device__ float g_gain_sum[GK];
__device__ float g_gain_cnt[GK];

__global__ void init_kernel() {
    int i = blockIdx.x * blockDim.x + threadIdx.x;
    if (i < KCODES * DIMS) g_shape_sum[i] = 0.f;
    if (i < KCODES)        g_shape_cnt[i] = 0.f;
    if (i < GK)  { g_gain_sum[i] = 0.f; g_gain_cnt[i] = 0.f; }
}

// ---------------- bf16 helpers ----------------
__device__ __forceinline__ unsigned pk_bf16x2(float lo, float hi) {
    unsigned r;
    asm("cvt.rn.bf16x2.f32 %0, %1, %2;" : "=r"(r) : "f"(hi), "f"(lo));
    return r;
}

__device__ __forceinline__ void mma_bf16(float c[4], uint4 a, unsigned b0, unsigned b1) {
    asm volatile(
        "mma.sync.aligned.m16n8k16.row.col.f32.bf16.bf16.f32 "
        "{%0,%1,%2,%3},{%4,%5,%6,%7},{%8,%9},{%0,%1,%2,%3};"
        : "+f"(c[0]), "+f"(c[1]), "+f"(c[2]), "+f"(c[3])
        : "r"(a.x), "r"(a.y), "r"(a.z), "r"(a.w), "r"(b0), "r"(b1));
}

// ---------------- prep: x -> A-fragment layout (bf16, m16n8k16) ------------
__global__ __launch_bounds__(256) void prep_x(const float* __restrict__ x) {
    int blk = blockIdx.x, tid = threadIdx.x;
    #pragma unroll
    for (int i = 0; i < 8; i++) {
        int f = tid + i * 256;
        int wr = f >> 9, ks = (f >> 5) & 15, lane = f & 31;
        int r = blk * 64 + wr * 16 + (lane >> 2);
        int k = ks * 16 + (lane & 3) * 2;
        const float* p0 = x + (size_t)r * DIMS + k;
        const float* p1 = x + (size_t)(r + 8) * DIMS + k;
        float2 v00 = *(const float2*)(p0);
        float2 v10 = *(const float2*)(p1);
        float2 v01 = *(const float2*)(p0 + 8);
        float2 v11 = *(const float2*)(p1 + 8);
        uint4 o;
        o.x = pk_bf16x2(v00.x, v00.y);
        o.y = pk_bf16x2(v10.x, v10.y);
        o.z = pk_bf16x2(v01.x, v01.y);
        o.w = pk_bf16x2(v11.x, v11.y);
        g_xfrag[blk * 2048 + f] = o;
    }
}

// ---------------- prep: cb -> paired B-fragment layout (bf16, k32 pairs) ---
// i = st*256 + kp*32 + lane; col = st*8 + (lane>>2); k = kp*32 + (lane&3)*2
// uint4 = frags for kspl=2kp (xy) and kspl=2kp+1 (zw)
__global__ __launch_bounds__(256) void prep_cb(const float* __restrict__ cb) {
    int i = blockIdx.x * 256 + threadIdx.x;   // 32768
    int lane = i & 31, kp = (i >> 5) & 7, st = i >> 8;
    int col = st * 8 + (lane >> 2);
    int k = kp * 32 + (lane & 3) * 2;
    const float* p = cb + (size_t)col * DIMS + k;
    uint4 o;
    o.x = pk_bf16x2(p[0],  p[1]);
    o.y = pk_bf16x2(p[8],  p[9]);
    o.z = pk_bf16x2(p[16], p[17]);
    o.w = pk_bf16x2(p[24], p[25]);
    g_bfrag4[i] = o;
}

// ---------------- top-3 insert with early reject ----------------
__device__ __forceinline__ void ins3(float* tv, int* tix, float v, int j) {
    if (v <= tv[2]) return;                   // common path: 1 compare
    if (v > tv[0]) {
        tv[2]=tv[1]; tix[2]=tix[1]; tv[1]=tv[0]; tix[1]=tix[0];
        tv[0]=v; tix[0]=j;
    } else if (v > tv[1]) {
        tv[2]=tv[1]; tix[2]=tix[1]; tv[1]=v; tix[1]=j;
    } else {
        tv[2]=v; tix[2]=j;
    }
}

// ---------------- main: bf16 MMA coarse + exact fp32 rescore + epilogue ----
__global__ __launch_bounds__(256, 2) void vq_main(
    const float* __restrict__ x,
    const float* __restrict__ cb,
    const float* __restrict__ gcb,
    float* __restrict__ out_q)
{
    extern __shared__ float sm[];
    uint4* saf  = (uint4*)sm;                 // 2048 uint4 (32 KB) A frags
    uint4* sbf4 = saf + 2048;                 // 2 x 1024 uint4 (32 KB) B dbl-buf
    float* cvv  = (float*)(sbf4 + 2048);      // 3072 candidate values (12 KB)
    int*   cix  = (int*)(cvv + 3072);         // 3072 candidate indices (12 KB)
    float* gains  = (float*)(cix + 3072);     // 64
    float* bval   = gains + GK;               // 64
    int*   bidx   = (int*)(bval + 64);        // 64
    float* bscale = (float*)(bidx + 64);      // 64

    const int tid = threadIdx.x, blk = blockIdx.x;
    const int lane = tid & 31, wid = tid >> 5;
    const int wr = wid & 1, wc = wid >> 1;    // 2 x 4 warp grid, M=32/warp
    const int row0 = blk * 64;

    // stage A fragments (32 KB, coalesced)
    #pragma unroll
    for (int i = 0; i < 8; i++)
        saf[tid + i * 256] = g_xfrag[blk * 2048 + tid + i * 256];
    if (tid < GK) gains[tid] = gcb[tid];

    // stage B chunk 0 (ci=0, kc=0): 1024 uint4, 4/thread
    #pragma unroll
    for (int i = 0; i < 4; i++) {
        int f = tid + i * 256;
        int stl = f >> 6, kpl = (f >> 5) & 1, ln = f & 31;
        sbf4[f - (f & 1023) + (stl * 2 + kpl) * 32 + ln] =
            g_bfrag4[(stl * 8 + kpl) * 32 + ln];
    }

    // 4 top-3 lists: [mt*2 + rowhalf]
    float tv[4][3]; int tx[4][3];
    #pragma unroll
    for (int l = 0; l < 4; l++)
        #pragma unroll
        for (int e = 0; e < 3; e++) { tv[l][e] = -3.4e38f; tx[l][e] = 0; }

    float acc[4][2][4];   // [st][mt][q]
    #pragma unroll
    for (int st = 0; st < 4; st++)
        #pragma unroll
        for (int mt = 0; mt < 2; mt++)
            #pragma unroll
            for (int q = 0; q < 4; q++) acc[st][mt][q] = 0.f;

    __syncthreads();

    const int NQ = CI_N * KC_N;               // 32 chunks
    for (int q = 0; q < NQ; q++) {
        int ci = q >> 2, kc = q & 3;
        uint4* sbf = sbf4 + (q & 1) * 1024;

        // stage next chunk into the other buffer (overlaps MMA below)
        if (q + 1 < NQ) {
            int ci1 = (q + 1) >> 2, kc1 = (q + 1) & 3;
            uint4* nb = sbf4 + ((q + 1) & 1) * 1024;
            #pragma unroll
            for (int i = 0; i < 4; i++) {
                int f = tid + i * 256;
                int stl = f >> 6, kpl = (f >> 5) & 1, ln = f & 31;
                nb[(stl * 2 + kpl) * 32 + ln] =
                    g_bfrag4[((ci1 * 16 + stl) * 8 + kc1 * 2 + kpl) * 32 + ln];
            }
        }

        #pragma unroll
        for (int kp = 0; kp < 2; kp++) {
            // one B uint4 read feeds 4 MMAs (2 ksteps x 2 M-tiles)
            uint4 B4[4];
            #pragma unroll
            for (int st = 0; st < 4; st++)
                B4[st] = sbf[((wc * 4 + st) * 2 + kp) * 32 + lane];
            #pragma unroll
            for (int half = 0; half < 2; half++) {
                int kspl = kp * 2 + half;
                uint4 A0 = saf[(wr * 2 + 0) * 512 + (kc * 4 + kspl) * 32 + lane];
                uint4 A1 = saf[(wr * 2 + 1) * 512 + (kc * 4 + kspl) * 32 + lane];
                #pragma unroll
                for (int st = 0; st < 4; st++) {
                    unsigned b0 = half ? B4[st].z : B4[st].x;
                    unsigned b1 = half ? B4[st].w : B4[st].y;
                    mma_bf16(acc[st][0], A0, b0, b1);
                    mma_bf16(acc[st][1], A1, b0, b1);
                }
            }
        }

        if (kc == 3) {
            // end of ci: coarse top-3 harvest into 4 lists
            #pragma unroll
            for (int st = 0; st < 4; st++) {
                int col = ci * 128 + wc * 32 + st * 8 + 2 * (lane & 3);
                #pragma unroll
                for (int mt = 0; mt < 2; mt++) {
                    ins3(tv[mt*2+0], tx[mt*2+0], acc[st][mt][0], col);
                    ins3(tv[mt*2+0], tx[mt*2+0], acc[st][mt][1], col + 1);
                    ins3(tv[mt*2+1], tx[mt*2+1], acc[st][mt][2], col);
                    ins3(tv[mt*2+1], tx[mt*2+1], acc[st][mt][3], col + 1);
                    acc[st][mt][0] = 0.f; acc[st][mt][1] = 0.f;
                    acc[st][mt][2] = 0.f; acc[st][mt][3] = 0.f;
                }
            }
        }
        __syncthreads();
    }

    // merge candidates to smem: 16 slots x 3 entries per row
    {
        int slot = wc * 4 + (lane & 3);
        #pragma unroll
        for (int l = 0; l < 4; l++) {
            int row = wr * 32 + (l >> 1) * 16 + (l & 1) * 8 + (lane >> 2);
            #pragma unroll
            for (int e = 0; e < 3; e++) {
                cvv[row * 48 + slot * 3 + e] = tv[l][e];
                cix[row * 48 + slot * 3 + e] = tx[l][e];
            }
        }
    }
    __syncthreads();

    // ---- exact fp32 rescore: 4 threads per row (12 entries each) ----
    {
        int row = tid >> 2;          // 0..63
        int sub = tid & 3;           // 0..3  (lanes row*4+sub share a warp)
        int base = row * 48 + sub * 12;

        float m = -3.4e38f;
        #pragma unroll
        for (int e = 0; e < 12; e++)
            m = fmaxf(m, cvv[base + e]);
        m = fmaxf(m, __shfl_xor_sync(0xffffffffu, m, 1));
        m = fmaxf(m, __shfl_xor_sync(0xffffffffu, m, 2));

        float best = -3.4e38f; int bj = 0x7fffffff;
        const float4* xr = (const float4*)(x + (size_t)(row0 + row) * DIMS);
        #pragma unroll
        for (int e = 0; e < 12; e++) {
            float c = cvv[base + e];
            if (c >= m - DELTA) {
                int j = cix[base + e];
                const float4* cr = (const float4*)(cb + (size_t)j * DIMS);
                float a0 = 0.f, a1 = 0.f, a2 = 0.f, a3 = 0.f;
                #pragma unroll 8
                for (int i = 0; i < 64; i++) {
                    float4 xv = xr[i], cw = cr[i];
                    a0 = fmaf(xv.x, cw.x, a0);
                    a1 = fmaf(xv.y, cw.y, a1);
                    a2 = fmaf(xv.z, cw.z, a2);
                    a3 = fmaf(xv.w, cw.w, a3);
                }
                float ex = (a0 + a1) + (a2 + a3);
                if (ex > best || (ex == best && j < bj)) { best = ex; bj = j; }
            }
        }
        #pragma unroll
        for (int off = 1; off < 4; off <<= 1) {
            float ov = __shfl_xor_sync(0xffffffffu, best, off);
            int   oj = __shfl_xor_sync(0xffffffffu, bj, off);
            if (ov > best || (ov == best && oj < bj)) { best = ov; bj = oj; }
        }

        if (sub == 0) {
            bval[row] = best; bidx[row] = bj;
            float g = logf(fmaxf(best, EPSF));
            float bd = 3.4e38f; int gi = 0;
            #pragma unroll
            for (int qq = 0; qq < GK; qq++) {
                float d = g - gains[qq];
                float d2 = d * d;
                if (d2 < bd) { bd = d2; gi = qq; }
            }
            atomicAdd(&g_gain_sum[gi], g);
            atomicAdd(&g_gain_cnt[gi], 1.f);
            atomicAdd(&g_shape_cnt[bj], 1.f);
            bscale[row] = expf(gains[gi]);
        }
    }
    __syncthreads();

    // ---- epilogue: quantize output + shape_sum scatter (float4) ----
    {
        int rr = tid >> 6;               // 0..3
        int d4 = (tid & 63) * 4;         // dim offset
        #pragma unroll 4
        for (int it = 0; it < 16; it++) {
            int r = it * 4 + rr;
            int k = bidx[r];
            float sc = bscale[r];
            float4 cvw = *(const float4*)(cb + (size_t)k * DIMS + d4);
            float4 xv  = *(const float4*)(x + (size_t)(row0 + r) * DIMS + d4);
            float4 o;
            o.x = sc * cvw.x; o.y = sc * cvw.y;
            o.z = sc * cvw.z; o.w = sc * cvw.w;
            *(float4*)(out_q + (size_t)(row0 + r) * DIMS + d4) = o;
            float* ss = &g_shape_sum[(size_t)k * DIMS + d4];
            atomicAdd(ss + 0, xv.x);
            atomicAdd(ss + 1, xv.y);
            atomicAdd(ss + 2, xv.z);
            atomicAdd(ss + 3, xv.w);
        }
    }
}

// ---------------- finalize: EMA updates ----------------
__device__ __forceinline__ float blockSum256(float v, float* red) {
    __syncthreads();
    int lane = threadIdx.x & 31, w = threadIdx.x >> 5;
    #pragma unroll
    for (int o = 16; o; o >>= 1) v += __shfl_xor_sync(0xffffffffu, v, o);
    if (lane == 0) red[w] = v;
    __syncthreads();
    if (w == 0) {
        float t = (lane < 8) ? red[lane] : 0.f;
        #pragma unroll
        for (int o = 4; o; o >>= 1) t += __shfl_xor_sync(0xffffffffu, t, o);
        if (lane == 0) red[0] = t;
    }
    __syncthreads();
    return red[0];
}

__global__ __launch_bounds__(256) void vq_finalize(
    const float* __restrict__ cb,   const float* __restrict__ gcb,
    const float* __restrict__ snum, const float* __restrict__ gnum,
    float* __restrict__ out_shape,  float* __restrict__ out_gain,
    float* __restrict__ out_snum,   float* __restrict__ out_gnum)
{
    __shared__ float red[8];
    int k = blockIdx.x, t = threadIdx.x;

    float s = g_shape_sum[k * DIMS + t];
    float ss = blockSum256(s * s, red);
    float denom = fmaxf(sqrtf(ss), EPSF);
    float upd = cb[k * DIMS + t] * DECAYF + (s / denom) * OMDF;
    float nn = blockSum256(upd * upd, red);
    float n2 = fmaxf(sqrtf(nn), 1e-12f);
    out_shape[k * DIMS + t] = upd / n2;

    if (t == 0)
        out_snum[k] = snum[k] * DECAYF + g_shape_cnt[k] * OMDF;

    if (k == 0 && t < GK) {
        float cnt  = g_gain_cnt[t];
        float gnew = g_gain_sum[t] / fmaxf(cnt, EPSF);
        out_gain[t] = gcb[t]  * DECAYF + gnew * OMDF;
        out_gnum[t] = gnum[t] * DECAYF + cnt  * OMDF;
    }
}

// ---------------- launch ----------------
extern "C" void kernel_launch(void* const* d_in, const int* in_sizes, int n_in,
                              void* d_out, int out_size) {
    const float* x    = (const float*)d_in[0];   // (48000, 256)
    const float* cb   = (const float*)d_in[1];   // (1024, 256)
    const float* gcb  = (const float*)d_in[2];   // (64,)
    const float* snum = (const float*)d_in[3];   // (1024,)
    const float* gnum = (const float*)d_in[4];   // (64,)

    float* out       = (float*)d_out;
    float* out_q     = out;                             // 12,288,000
    float* out_shape = out_q + (size_t)N_ROWS * DIMS;   // 262,144
    float* out_gain  = out_shape + KCODES * DIMS;       // 64
    float* out_snum  = out_gain + GK;                   // 1024
    float* out_gnum  = out_snum + KCODES;               // 64

    init_kernel<<<(KCODES * DIMS + 255) / 256, 256>>>();
    prep_x<<<NB, 256>>>(x);
    prep_cb<<<128, 256>>>(cb);

    // smem: A 32768 + B dbl 32768 + cvv 12288 + cix 12288 + misc 1024 = 91136 B
    size_t smem = 91136;
    cudaFuncSetAttribute(vq_main, cudaFuncAttributeMaxDynamicSharedMemorySize,
                         (int)smem);
    vq_main<<<NB, 256, smem>>>(x, cb, gcb, out_q);

    vq_finalize<<<KCODES, 256>>>(cb, gcb, snum, gnum,
                                 out_shape, out_gain, out_snum, out_gnum);
}

// round 15
// speedup vs baseline: 1.5622x; 1.0475x over previous
#include <cuda_runtime.h>
#include <math.h>

#define N_ROWS 48000
#define DIMS   256
#define KCODES 1024
#define GK     64
#define NB     (N_ROWS / 64)        // 750 row-blocks
#define CI_N   8                    // col iterations (128 cols each)
#define KC_N   4                    // k chunks (64 k each)
#define DELTA  1.0f                 // rescore margin (~11 sigma of bf16 noise)
#define DECAYF 0.99f
#define OMDF   0.01f
#define EPSF   1e-5f

// ---------------- scratch (static device globals; no runtime alloc) --------
__device__ uint4 g_xfrag[NB * 2048];    // A frags bf16 24.5 MB
__device__ uint4 g_bfrag4[32768];       // B frags bf16 paired k32 512 KB
__device__ float g_shape_sum[KCODES * DIMS];
__device__ float g_shape_cnt[KCODES];
__device__ float g_gain_sum[GK];
__device__ float g_gain_cnt[GK];

__global__ void init_kernel() {
    int i = blockIdx.x * blockDim.x + threadIdx.x;
    if (i < KCODES * DIMS) g_shape_sum[i] = 0.f;
    if (i < KCODES)        g_shape_cnt[i] = 0.f;
    if (i < GK)  { g_gain_sum[i] = 0.f; g_gain_cnt[i] = 0.f; }
}

// ---------------- bf16 helpers ----------------
__device__ __forceinline__ unsigned pk_bf16x2(float lo, float hi) {
    unsigned r;
    asm("cvt.rn.bf16x2.f32 %0, %1, %2;" : "=r"(r) : "f"(hi), "f"(lo));
    return r;
}

__device__ __forceinline__ void mma_bf16(float c[4], uint4 a, unsigned b0, unsigned b1) {
    asm volatile(
        "mma.sync.aligned.m16n8k16.row.col.f32.bf16.bf16.f32 "
        "{%0,%1,%2,%3},{%4,%5,%6,%7},{%8,%9},{%0,%1,%2,%3};"
        : "+f"(c[0]), "+f"(c[1]), "+f"(c[2]), "+f"(c[3])
        : "r"(a.x), "r"(a.y), "r"(a.z), "r"(a.w), "r"(b0), "r"(b1));
}

// vectorized global reduction: one RED.128 instead of 4 scalar REDG
__device__ __forceinline__ void red_add_v4(float* p, float4 v) {
    asm volatile("red.global.add.v4.f32 [%0], {%1,%2,%3,%4};"
                 :: "l"(p), "f"(v.x), "f"(v.y), "f"(v.z), "f"(v.w)
                 : "memory");
}

// ---------------- prep: x -> A-fragment layout (bf16, m16n8k16) ------------
__global__ __launch_bounds__(256) void prep_x(const float* __restrict__ x) {
    int blk = blockIdx.x, tid = threadIdx.x;
    #pragma unroll
    for (int i = 0; i < 8; i++) {
        int f = tid + i * 256;
        int wr = f >> 9, ks = (f >> 5) & 15, lane = f & 31;
        int r = blk * 64 + wr * 16 + (lane >> 2);
        int k = ks * 16 + (lane & 3) * 2;
        const float* p0 = x + (size_t)r * DIMS + k;
        const float* p1 = x + (size_t)(r + 8) * DIMS + k;
        float2 v00 = *(const float2*)(p0);
        float2 v10 = *(const float2*)(p1);
        float2 v01 = *(const float2*)(p0 + 8);
        float2 v11 = *(const float2*)(p1 + 8);
        uint4 o;
        o.x = pk_bf16x2(v00.x, v00.y);
        o.y = pk_bf16x2(v10.x, v10.y);
        o.z = pk_bf16x2(v01.x, v01.y);
        o.w = pk_bf16x2(v11.x, v11.y);
        g_xfrag[blk * 2048 + f] = o;
    }
}

// ---------------- prep: cb -> paired B-fragment layout (bf16, k32 pairs) ---
__global__ __launch_bounds__(256) void prep_cb(const float* __restrict__ cb) {
    int i = blockIdx.x * 256 + threadIdx.x;   // 32768
    int lane = i & 31, kp = (i >> 5) & 7, st = i >> 8;
    int col = st * 8 + (lane >> 2);
    int k = kp * 32 + (lane & 3) * 2;
    const float* p = cb + (size_t)col * DIMS + k;
    uint4 o;
    o.x = pk_bf16x2(p[0],  p[1]);
    o.y = pk_bf16x2(p[8],  p[9]);
    o.z = pk_bf16x2(p[16], p[17]);
    o.w = pk_bf16x2(p[24], p[25]);
    g_bfrag4[i] = o;
}

// ---------------- top-3 insert with early reject ----------------
__device__ __forceinline__ void ins3(float* tv, int* tix, float v, int j) {
    if (v <= tv[2]) return;                   // common path: 1 compare
    if (v > tv[0]) {
        tv[2]=tv[1]; tix[2]=tix[1]; tv[1]=tv[0]; tix[1]=tix[0];
        tv[0]=v; tix[0]=j;
    } else if (v > tv[1]) {
        tv[2]=tv[1]; tix[2]=tix[1]; tv[1]=v; tix[1]=j;
    } else {
        tv[2]=v; tix[2]=j;
    }
}

// ---------------- main: bf16 MMA coarse + exact fp32 rescore + epilogue ----
__global__ __launch_bounds__(256, 2) void vq_main(
    const float* __restrict__ x,
    const float* __restrict__ cb,
    const float* __restrict__ gcb,
    float* __restrict__ out_q)
{
    extern __shared__ float sm[];
    uint4* saf  = (uint4*)sm;                 // 2048 uint4 (32 KB) A frags
    uint4* sbf4 = saf + 2048;                 // 2 x 1024 uint4 (32 KB) B dbl-buf
    float* cvv  = (float*)(sbf4 + 2048);      // 3072 candidate values (12 KB)
    int*   cix  = (int*)(cvv + 3072);         // 3072 candidate indices (12 KB)
    float* gains  = (float*)(cix + 3072);     // 64
    float* bval   = gains + GK;               // 64
    int*   bidx   = (int*)(bval + 64);        // 64
    float* bscale = (float*)(bidx + 64);      // 64

    const int tid = threadIdx.x, blk = blockIdx.x;
    const int lane = tid & 31, wid = tid >> 5;
    const int wr = wid & 1, wc = wid >> 1;    // 2 x 4 warp grid, M=32/warp
    const int row0 = blk * 64;

    // stage A fragments (32 KB, coalesced)
    #pragma unroll
    for (int i = 0; i < 8; i++)
        saf[tid + i * 256] = g_xfrag[blk * 2048 + tid + i * 256];
    if (tid < GK) gains[tid] = gcb[tid];

    // stage B chunk 0 (ci=0, kc=0): 1024 uint4, 4/thread
    #pragma unroll
    for (int i = 0; i < 4; i++) {
        int f = tid + i * 256;
        int stl = f >> 6, kpl = (f >> 5) & 1, ln = f & 31;
        sbf4[f - (f & 1023) + (stl * 2 + kpl) * 32 + ln] =
            g_bfrag4[(stl * 8 + kpl) * 32 + ln];
    }

    // 4 top-3 lists: [mt*2 + rowhalf]
    float tv[4][3]; int tx[4][3];
    #pragma unroll
    for (int l = 0; l < 4; l++)
        #pragma unroll
        for (int e = 0; e < 3; e++) { tv[l][e] = -3.4e38f; tx[l][e] = 0; }

    float acc[4][2][4];   // [st][mt][q]
    #pragma unroll
    for (int st = 0; st < 4; st++)
        #pragma unroll
        for (int mt = 0; mt < 2; mt++)
            #pragma unroll
            for (int q = 0; q < 4; q++) acc[st][mt][q] = 0.f;

    __syncthreads();

    const int NQ = CI_N * KC_N;               // 32 chunks
    for (int q = 0; q < NQ; q++) {
        int ci = q >> 2, kc = q & 3;
        uint4* sbf = sbf4 + (q & 1) * 1024;

        // stage next chunk into the other buffer (overlaps MMA below)
        if (q + 1 < NQ) {
            int ci1 = (q + 1) >> 2, kc1 = (q + 1) & 3;
            uint4* nb = sbf4 + ((q + 1) & 1) * 1024;
            #pragma unroll
            for (int i = 0; i < 4; i++) {
                int f = tid + i * 256;
                int stl = f >> 6, kpl = (f >> 5) & 1, ln = f & 31;
                nb[(stl * 2 + kpl) * 32 + ln] =
                    g_bfrag4[((ci1 * 16 + stl) * 8 + kc1 * 2 + kpl) * 32 + ln];
            }
        }

        #pragma unroll
        for (int kp = 0; kp < 2; kp++) {
            uint4 B4[4];
            #pragma unroll
            for (int st = 0; st < 4; st++)
                B4[st] = sbf[((wc * 4 + st) * 2 + kp) * 32 + lane];
            #pragma unroll
            for (int half = 0; half < 2; half++) {
                int kspl = kp * 2 + half;
                uint4 A0 = saf[(wr * 2 + 0) * 512 + (kc * 4 + kspl) * 32 + lane];
                uint4 A1 = saf[(wr * 2 + 1) * 512 + (kc * 4 + kspl) * 32 + lane];
                #pragma unroll
                for (int st = 0; st < 4; st++) {
                    unsigned b0 = half ? B4[st].z : B4[st].x;
                    unsigned b1 = half ? B4[st].w : B4[st].y;
                    mma_bf16(acc[st][0], A0, b0, b1);
                    mma_bf16(acc[st][1], A1, b0, b1);
                }
            }
        }

        if (kc == 3) {
            // end of ci: coarse top-3 harvest into 4 lists
            #pragma unroll
            for (int st = 0; st < 4; st++) {
                int col = ci * 128 + wc * 32 + st * 8 + 2 * (lane & 3);
                #pragma unroll
                for (int mt = 0; mt < 2; mt++) {
                    ins3(tv[mt*2+0], tx[mt*2+0], acc[st][mt][0], col);
                    ins3(tv[mt*2+0], tx[mt*2+0], acc[st][mt][1], col + 1);
                    ins3(tv[mt*2+1], tx[mt*2+1], acc[st][mt][2], col);
                    ins3(tv[mt*2+1], tx[mt*2+1], acc[st][mt][3], col + 1);
                    acc[st][mt][0] = 0.f; acc[st][mt][1] = 0.f;
                    acc[st][mt][2] = 0.f; acc[st][mt][3] = 0.f;
                }
            }
        }
        __syncthreads();
    }

    // merge candidates to smem: 16 slots x 3 entries per row
    {
        int slot = wc * 4 + (lane & 3);
        #pragma unroll
        for (int l = 0; l < 4; l++) {
            int row = wr * 32 + (l >> 1) * 16 + (l & 1) * 8 + (lane >> 2);
            #pragma unroll
            for (int e = 0; e < 3; e++) {
                cvv[row * 48 + slot * 3 + e] = tv[l][e];
                cix[row * 48 + slot * 3 + e] = tx[l][e];
            }
        }
    }
    __syncthreads();

    // ---- exact fp32 rescore: 4 threads per row (12 entries each) ----
    {
        int row = tid >> 2;          // 0..63
        int sub = tid & 3;           // 0..3  (lanes row*4+sub share a warp)
        int base = row * 48 + sub * 12;

        float m = -3.4e38f;
        #pragma unroll
        for (int e = 0; e < 12; e++)
            m = fmaxf(m, cvv[base + e]);
        m = fmaxf(m, __shfl_xor_sync(0xffffffffu, m, 1));
        m = fmaxf(m, __shfl_xor_sync(0xffffffffu, m, 2));

        float best = -3.4e38f; int bj = 0x7fffffff;
        const float4* xr = (const float4*)(x + (size_t)(row0 + row) * DIMS);
        #pragma unroll
        for (int e = 0; e < 12; e++) {
            float c = cvv[base + e];
            if (c >= m - DELTA) {
                int j = cix[base + e];
                const float4* cr = (const float4*)(cb + (size_t)j * DIMS);
                float a0 = 0.f, a1 = 0.f, a2 = 0.f, a3 = 0.f;
                #pragma unroll 8
                for (int i = 0; i < 64; i++) {
                    float4 xv = xr[i], cw = cr[i];
                    a0 = fmaf(xv.x, cw.x, a0);
                    a1 = fmaf(xv.y, cw.y, a1);
                    a2 = fmaf(xv.z, cw.z, a2);
                    a3 = fmaf(xv.w, cw.w, a3);
                }
                float ex = (a0 + a1) + (a2 + a3);
                if (ex > best || (ex == best && j < bj)) { best = ex; bj = j; }
            }
        }
        #pragma unroll
        for (int off = 1; off < 4; off <<= 1) {
            float ov = __shfl_xor_sync(0xffffffffu, best, off);
            int   oj = __shfl_xor_sync(0xffffffffu, bj, off);
            if (ov > best || (ov == best && oj < bj)) { best = ov; bj = oj; }
        }

        if (sub == 0) {
            bval[row] = best; bidx[row] = bj;
            float g = logf(fmaxf(best, EPSF));
            float bd = 3.4e38f; int gi = 0;
            #pragma unroll
            for (int qq = 0; qq < GK; qq++) {
                float d = g - gains[qq];
                float d2 = d * d;
                if (d2 < bd) { bd = d2; gi = qq; }
            }
            atomicAdd(&g_gain_sum[gi], g);
            atomicAdd(&g_gain_cnt[gi], 1.f);
            atomicAdd(&g_shape_cnt[bj], 1.f);
            bscale[row] = expf(gains[gi]);
        }
    }
    __syncthreads();

    // ---- epilogue: quantize output + shape_sum scatter (RED.128) ----
    {
        int rr = tid >> 6;               // 0..3
        int d4 = (tid & 63) * 4;         // dim offset
        #pragma unroll 4
        for (int it = 0; it < 16; it++) {
            int r = it * 4 + rr;
            int k = bidx[r];
            float sc = bscale[r];
            float4 cvw = *(const float4*)(cb + (size_t)k * DIMS + d4);
            float4 xv  = *(const float4*)(x + (size_t)(row0 + r) * DIMS + d4);
            float4 o;
            o.x = sc * cvw.x; o.y = sc * cvw.y;
            o.z = sc * cvw.z; o.w = sc * cvw.w;
            *(float4*)(out_q + (size_t)(row0 + r) * DIMS + d4) = o;
            red_add_v4(&g_shape_sum[(size_t)k * DIMS + d4], xv);
        }
    }
}

// ---------------- finalize: EMA updates ----------------
__device__ __forceinline__ float blockSum256(float v, float* red) {
    __syncthreads();
    int lane = threadIdx.x & 31, w = threadIdx.x >> 5;
    #pragma unroll
    for (int o = 16; o; o >>= 1) v += __shfl_xor_sync(0xffffffffu, v, o);
    if (lane == 0) red[w] = v;
    __syncthreads();
    if (w == 0) {
        float t = (lane < 8) ? red[lane] : 0.f;
        #pragma unroll
        for (int o = 4; o; o >>= 1) t += __shfl_xor_sync(0xffffffffu, t, o);
        if (lane == 0) red[0] = t;
    }
    __syncthreads();
    return red[0];
}

__global__ __launch_bounds__(256) void vq_finalize(
    const float* __restrict__ cb,   const float* __restrict__ gcb,
    const float* __restrict__ snum, const float* __restrict__ gnum,
    float* __restrict__ out_shape,  float* __restrict__ out_gain,
    float* __restrict__ out_snum,   float* __restrict__ out_gnum)
{
    __shared__ float red[8];
    int k = blockIdx.x, t = threadIdx.x;

    float s = g_shape_sum[k * DIMS + t];
    float ss = blockSum256(s * s, red);
    float denom = fmaxf(sqrtf(ss), EPSF);
    float upd = cb[k * DIMS + t] * DECAYF + (s / denom) * OMDF;
    float nn = blockSum256(upd * upd, red);
    float n2 = fmaxf(sqrtf(nn), 1e-12f);
    out_shape[k * DIMS + t] = upd / n2;

    if (t == 0)
        out_snum[k] = snum[k] * DECAYF + g_shape_cnt[k] * OMDF;

    if (k == 0 && t < GK) {
        float cnt  = g_gain_cnt[t];
        float gnew = g_gain_sum[t] / fmaxf(cnt, EPSF);
        out_gain[t] = gcb[t]  * DECAYF + gnew * OMDF;
        out_gnum[t] = gnum[t] * DECAYF + cnt  * OMDF;
    }
}

// ---------------- launch ----------------
extern "C" void kernel_launch(void* const* d_in, const int* in_sizes, int n_in,
                              void* d_out, int out_size) {
    const float* x    = (const float*)d_in[0];   // (48000, 256)
    const float* cb   = (const float*)d_in[1];   // (1024, 256)
    const float* gcb  = (const float*)d_in[2];   // (64,)
    const float* snum = (const float*)d_in[3];   // (1024,)
    const float* gnum = (const float*)d_in[4];   // (64,)

    float* out       = (float*)d_out;
    float* out_q     = out;                             // 12,288,000
    float* out_shape = out_q + (size_t)N_ROWS * DIMS;   // 262,144
    float* out_gain  = out_shape + KCODES * DIMS;       // 64
    float* out_snum  = out_gain + GK;                   // 1024
    float* out_gnum  = out_snum + KCODES;               // 64

    init_kernel<<<(KCODES * DIMS + 255) / 256, 256>>>();
    prep_x<<<NB, 256>>>(x);
    prep_cb<<<128, 256>>>(cb);

    // smem: A 32768 + B dbl 32768 + cvv 12288 + cix 12288 + misc 1024 = 91136 B
    size_t smem = 91136;
    cudaFuncSetAttribute(vq_main, cudaFuncAttributeMaxDynamicSharedMemorySize,
                         (int)smem);
    vq_main<<<NB, 256, smem>>>(x, cb, gcb, out_q);

    vq_finalize<<<KCODES, 256>>>(cb, gcb, snum, gnum,
                                 out_shape, out_gain, out_snum, out_gnum);
}

// round 16
// speedup vs baseline: 1.7436x; 1.1161x over previous
#include <cuda_runtime.h>
#include <math.h>

#define N_ROWS 48000
#define DIMS   256
#define KCODES 1024
#define GK     64
#define NB     (N_ROWS / 64)        // 750 row-blocks
#define CI_N   8                    // col iterations (128 cols each)
#define DELTA  1.0f                 // rescore margin (~11 sigma of bf16 noise)
#define DECAYF 0.99f
#define OMDF   0.01f
#define EPSF   1e-5f

// ---------------- scratch (static device globals; no runtime alloc) --------
__device__ uint4 g_xfrag[NB * 2048];    // A frags bf16 24.5 MB
__device__ uint4 g_bfrag4[32768];       // B frags bf16 paired k32 512 KB
__device__ float g_shape_sum[KCODES * DIMS];
__device__ float g_shape_cnt[KCODES];
__device__ float g_gain_sum[GK];
__device__ float g_gain_cnt[GK];

__global__ void init_kernel() {
    int i = blockIdx.x * blockDim.x + threadIdx.x;
    if (i < KCODES * DIMS) g_shape_sum[i] = 0.f;
    if (i < KCODES)        g_shape_cnt[i] = 0.f;
    if (i < GK)  { g_gain_sum[i] = 0.f; g_gain_cnt[i] = 0.f; }
}

// ---------------- bf16 helpers ----------------
__device__ __forceinline__ unsigned pk_bf16x2(float lo, float hi) {
    unsigned r;
    asm("cvt.rn.bf16x2.f32 %0, %1, %2;" : "=r"(r) : "f"(hi), "f"(lo));
    return r;
}

__device__ __forceinline__ void mma_bf16(float c[4], uint4 a, unsigned b0, unsigned b1) {
    asm volatile(
        "mma.sync.aligned.m16n8k16.row.col.f32.bf16.bf16.f32 "
        "{%0,%1,%2,%3},{%4,%5,%6,%7},{%8,%9},{%0,%1,%2,%3};"
        : "+f"(c[0]), "+f"(c[1]), "+f"(c[2]), "+f"(c[3])
        : "r"(a.x), "r"(a.y), "r"(a.z), "r"(a.w), "r"(b0), "r"(b1));
}

// vectorized global reduction: one RED.128 instead of 4 scalar REDG
__device__ __forceinline__ void red_add_v4(float* p, float4 v) {
    asm volatile("red.global.add.v4.f32 [%0], {%1,%2,%3,%4};"
                 :: "l"(p), "f"(v.x), "f"(v.y), "f"(v.z), "f"(v.w)
                 : "memory");
}

// pack code index (10 bits) into low mantissa bits; ordering preserved to
// ~1.2e-4 relative, irrelevant vs bf16 noise (0.09) and margin (1.0).
__device__ __forceinline__ float packvi(float v, int col) {
    return __uint_as_float((__float_as_uint(v) & 0xFFFFFC00u) | (unsigned)col);
}

// ---------------- prep: x -> A-fragment layout (bf16, m16n8k16) ------------
__global__ __launch_bounds__(256) void prep_x(const float* __restrict__ x) {
    int blk = blockIdx.x, tid = threadIdx.x;
    #pragma unroll
    for (int i = 0; i < 8; i++) {
        int f = tid + i * 256;
        int wr = f >> 9, ks = (f >> 5) & 15, lane = f & 31;
        int r = blk * 64 + wr * 16 + (lane >> 2);
        int k = ks * 16 + (lane & 3) * 2;
        const float* p0 = x + (size_t)r * DIMS + k;
        const float* p1 = x + (size_t)(r + 8) * DIMS + k;
        float2 v00 = *(const float2*)(p0);
        float2 v10 = *(const float2*)(p1);
        float2 v01 = *(const float2*)(p0 + 8);
        float2 v11 = *(const float2*)(p1 + 8);
        uint4 o;
        o.x = pk_bf16x2(v00.x, v00.y);
        o.y = pk_bf16x2(v10.x, v10.y);
        o.z = pk_bf16x2(v01.x, v01.y);
        o.w = pk_bf16x2(v11.x, v11.y);
        g_xfrag[blk * 2048 + f] = o;
    }
}

// ---------------- prep: cb -> paired B-fragment layout (bf16, k32 pairs) ---
__global__ __launch_bounds__(256) void prep_cb(const float* __restrict__ cb) {
    int i = blockIdx.x * 256 + threadIdx.x;   // 32768
    int lane = i & 31, kp = (i >> 5) & 7, st = i >> 8;
    int col = st * 8 + (lane >> 2);
    int k = kp * 32 + (lane & 3) * 2;
    const float* p = cb + (size_t)col * DIMS + k;
    uint4 o;
    o.x = pk_bf16x2(p[0],  p[1]);
    o.y = pk_bf16x2(p[8],  p[9]);
    o.z = pk_bf16x2(p[16], p[17]);
    o.w = pk_bf16x2(p[24], p[25]);
    g_bfrag4[i] = o;
}

// ---------------- top-3 insert (packed value+index), early reject ----------
__device__ __forceinline__ void ins3p(float* tv, float v) {
    if (v <= tv[2]) return;                   // common path: 1 compare
    if (v > tv[0])      { tv[2] = tv[1]; tv[1] = tv[0]; tv[0] = v; }
    else if (v > tv[1]) { tv[2] = tv[1]; tv[1] = v; }
    else                { tv[2] = v; }
}

// ---------------- main: bf16 MMA coarse + exact fp32 rescore + epilogue ----
__global__ __launch_bounds__(256, 2) void vq_main(
    const float* __restrict__ x,
    const float* __restrict__ cb,
    const float* __restrict__ gcb,
    float* __restrict__ out_q)
{
    extern __shared__ float sm[];
    uint4* saf  = (uint4*)sm;                 // 2048 uint4 (32 KB) A frags
    uint4* sbf4 = saf + 2048;                 // 4 x 1024 uint4 (64 KB) B bufs
    float* cvv  = (float*)(sbf4 + 4096);      // 3072 packed candidates (12 KB)
    float* gains  = cvv + 3072;               // 64
    int*   bidx   = (int*)(gains + GK);       // 64
    float* bscale = (float*)(bidx + 64);      // 64

    const int tid = threadIdx.x, blk = blockIdx.x;
    const int lane = tid & 31, wid = tid >> 5;
    const int wr = wid & 1, wc = wid >> 1;    // 2 x 4 warp grid, M=32/warp
    const int row0 = blk * 64;

    // stage A fragments (32 KB, coalesced)
    #pragma unroll
    for (int i = 0; i < 8; i++)
        saf[tid + i * 256] = g_xfrag[blk * 2048 + tid + i * 256];
    if (tid < GK) gains[tid] = gcb[tid];

    // prologue: stage chunks 0 and 1 (ci=0, kc=0/1) into buffers 0,1
    #pragma unroll
    for (int i = 0; i < 8; i++) {
        int f = tid + i * 256;               // 0..2047
        int ch = f >> 10;                    // chunk 0/1
        int g = f & 1023;
        int stl = g >> 6, kpl = (g >> 5) & 1, ln = g & 31;
        sbf4[ch * 1024 + g] = g_bfrag4[(stl * 8 + ch * 2 + kpl) * 32 + ln];
    }

    // 4 top-3 lists of packed value|index: [mt*2 + rowhalf]
    float tv[4][3];
    #pragma unroll
    for (int l = 0; l < 4; l++)
        #pragma unroll
        for (int e = 0; e < 3; e++) tv[l][e] = -3.4e38f;

    float acc[4][2][4];   // [st][mt][q]
    #pragma unroll
    for (int st = 0; st < 4; st++)
        #pragma unroll
        for (int mt = 0; mt < 2; mt++)
            #pragma unroll
            for (int q = 0; q < 4; q++) acc[st][mt][q] = 0.f;

    __syncthreads();

    // 16 pairs of chunks; 1 barrier per pair (16 barriers total)
    for (int p = 0; p < 16; p++) {
        int q0 = 2 * p;

        // stage pair p+1 (chunks q0+2, q0+3) into the other two buffers.
        // Safe: buffer (q0+2)&3 was last read in pair p-1, finished before
        // the barrier that ended pair p-1.
        if (p < 15) {
            #pragma unroll
            for (int c = 0; c < 2; c++) {
                int qs = q0 + 2 + c;
                int ci1 = qs >> 2, kc1 = qs & 3;
                uint4* nb = sbf4 + (qs & 3) * 1024;
                #pragma unroll
                for (int i = 0; i < 4; i++) {
                    int f = tid + i * 256;
                    int stl = f >> 6, kpl = (f >> 5) & 1, ln = f & 31;
                    nb[f] = g_bfrag4[((ci1 * 16 + stl) * 8 + kc1 * 2 + kpl) * 32 + ln];
                }
            }
        }

        // compute chunks q0, q0+1
        #pragma unroll
        for (int h = 0; h < 2; h++) {
            int q = q0 + h;
            int kc = q & 3;
            uint4* sbf = sbf4 + (q & 3) * 1024;
            #pragma unroll
            for (int kp = 0; kp < 2; kp++) {
                uint4 B4[4];
                #pragma unroll
                for (int st = 0; st < 4; st++)
                    B4[st] = sbf[((wc * 4 + st) * 2 + kp) * 32 + lane];
                #pragma unroll
                for (int half = 0; half < 2; half++) {
                    int kspl = kp * 2 + half;
                    uint4 A0 = saf[(wr * 2 + 0) * 512 + (kc * 4 + kspl) * 32 + lane];
                    uint4 A1 = saf[(wr * 2 + 1) * 512 + (kc * 4 + kspl) * 32 + lane];
                    #pragma unroll
                    for (int st = 0; st < 4; st++) {
                        unsigned b0 = half ? B4[st].z : B4[st].x;
                        unsigned b1 = half ? B4[st].w : B4[st].y;
                        mma_bf16(acc[st][0], A0, b0, b1);
                        mma_bf16(acc[st][1], A1, b0, b1);
                    }
                }
            }
        }

        // end of ci every other pair: harvest packed top-3
        if (p & 1) {
            int ci = q0 >> 2;
            #pragma unroll
            for (int st = 0; st < 4; st++) {
                int col = ci * 128 + wc * 32 + st * 8 + 2 * (lane & 3);
                #pragma unroll
                for (int mt = 0; mt < 2; mt++) {
                    ins3p(tv[mt*2+0], packvi(acc[st][mt][0], col));
                    ins3p(tv[mt*2+0], packvi(acc[st][mt][1], col + 1));
                    ins3p(tv[mt*2+1], packvi(acc[st][mt][2], col));
                    ins3p(tv[mt*2+1], packvi(acc[st][mt][3], col + 1));
                    acc[st][mt][0] = 0.f; acc[st][mt][1] = 0.f;
                    acc[st][mt][2] = 0.f; acc[st][mt][3] = 0.f;
                }
            }
        }
        __syncthreads();
    }

    // merge candidates to smem: 16 slots x 3 packed entries per row
    {
        int slot = wc * 4 + (lane & 3);
        #pragma unroll
        for (int l = 0; l < 4; l++) {
            int row = wr * 32 + (l >> 1) * 16 + (l & 1) * 8 + (lane >> 2);
            #pragma unroll
            for (int e = 0; e < 3; e++)
                cvv[row * 48 + slot * 3 + e] = tv[l][e];
        }
    }
    __syncthreads();

    // ---- exact fp32 rescore: 4 threads per row (12 packed entries each) ----
    {
        int row = tid >> 2;          // 0..63
        int sub = tid & 3;           // 0..3  (lanes row*4+sub share a warp)
        int base = row * 48 + sub * 12;

        float m = -3.4e38f;
        #pragma unroll
        for (int e = 0; e < 12; e++)
            m = fmaxf(m, cvv[base + e]);
        m = fmaxf(m, __shfl_xor_sync(0xffffffffu, m, 1));
        m = fmaxf(m, __shfl_xor_sync(0xffffffffu, m, 2));

        float best = -3.4e38f; int bj = 0x7fffffff;
        const float4* xr = (const float4*)(x + (size_t)(row0 + row) * DIMS);
        #pragma unroll
        for (int e = 0; e < 12; e++) {
            float c = cvv[base + e];
            if (c >= m - DELTA) {
                int j = (int)(__float_as_uint(c) & 1023u);
                const float4* cr = (const float4*)(cb + (size_t)j * DIMS);
                float a0 = 0.f, a1 = 0.f, a2 = 0.f, a3 = 0.f;
                #pragma unroll 8
                for (int i = 0; i < 64; i++) {
                    float4 xv = xr[i], cw = cr[i];
                    a0 = fmaf(xv.x, cw.x, a0);
                    a1 = fmaf(xv.y, cw.y, a1);
                    a2 = fmaf(xv.z, cw.z, a2);
                    a3 = fmaf(xv.w, cw.w, a3);
                }
                float ex = (a0 + a1) + (a2 + a3);
                if (ex > best || (ex == best && j < bj)) { best = ex; bj = j; }
            }
        }
        #pragma unroll
        for (int off = 1; off < 4; off <<= 1) {
            float ov = __shfl_xor_sync(0xffffffffu, best, off);
            int   oj = __shfl_xor_sync(0xffffffffu, bj, off);
            if (ov > best || (ov == best && oj < bj)) { best = ov; bj = oj; }
        }

        if (sub == 0) {
            bidx[row] = bj;
            float g = logf(fmaxf(best, EPSF));
            float bd = 3.4e38f; int gi = 0;
            #pragma unroll
            for (int qq = 0; qq < GK; qq++) {
                float d = g - gains[qq];
                float d2 = d * d;
                if (d2 < bd) { bd = d2; gi = qq; }
            }
            atomicAdd(&g_gain_sum[gi], g);
            atomicAdd(&g_gain_cnt[gi], 1.f);
            atomicAdd(&g_shape_cnt[bj], 1.f);
            bscale[row] = expf(gains[gi]);
        }
    }
    __syncthreads();

    // ---- epilogue: quantize output + shape_sum scatter (RED.128) ----
    {
        int rr = tid >> 6;               // 0..3
        int d4 = (tid & 63) * 4;         // dim offset
        #pragma unroll 4
        for (int it = 0; it < 16; it++) {
            int r = it * 4 + rr;
            int k = bidx[r];
            float sc = bscale[r];
            float4 cvw = *(const float4*)(cb + (size_t)k * DIMS + d4);
            float4 xv  = *(const float4*)(x + (size_t)(row0 + r) * DIMS + d4);
            float4 o;
            o.x = sc * cvw.x; o.y = sc * cvw.y;
            o.z = sc * cvw.z; o.w = sc * cvw.w;
            *(float4*)(out_q + (size_t)(row0 + r) * DIMS + d4) = o;
            red_add_v4(&g_shape_sum[(size_t)k * DIMS + d4], xv);
        }
    }
}

// ---------------- finalize: EMA updates ----------------
__device__ __forceinline__ float blockSum256(float v, float* red) {
    __syncthreads();
    int lane = threadIdx.x & 31, w = threadIdx.x >> 5;
    #pragma unroll
    for (int o = 16; o; o >>= 1) v += __shfl_xor_sync(0xffffffffu, v, o);
    if (lane == 0) red[w] = v;
    __syncthreads();
    if (w == 0) {
        float t = (lane < 8) ? red[lane] : 0.f;
        #pragma unroll
        for (int o = 4; o; o >>= 1) t += __shfl_xor_sync(0xffffffffu, t, o);
        if (lane == 0) red[0] = t;
    }
    __syncthreads();
    return red[0];
}

__global__ __launch_bounds__(256) void vq_finalize(
    const float* __restrict__ cb,   const float* __restrict__ gcb,
    const float* __restrict__ snum, const float* __restrict__ gnum,
    float* __restrict__ out_shape,  float* __restrict__ out_gain,
    float* __restrict__ out_snum,   float* __restrict__ out_gnum)
{
    __shared__ float red[8];
    int k = blockIdx.x, t = threadIdx.x;

    float s = g_shape_sum[k * DIMS + t];
    float ss = blockSum256(s * s, red);
    float denom = fmaxf(sqrtf(ss), EPSF);
    float upd = cb[k * DIMS + t] * DECAYF + (s / denom) * OMDF;
    float nn = blockSum256(upd * upd, red);
    float n2 = fmaxf(sqrtf(nn), 1e-12f);
    out_shape[k * DIMS + t] = upd / n2;

    if (t == 0)
        out_snum[k] = snum[k] * DECAYF + g_shape_cnt[k] * OMDF;

    if (k == 0 && t < GK) {
        float cnt  = g_gain_cnt[t];
        float gnew = g_gain_sum[t] / fmaxf(cnt, EPSF);
        out_gain[t] = gcb[t]  * DECAYF + gnew * OMDF;
        out_gnum[t] = gnum[t] * DECAYF + cnt  * OMDF;
    }
}

// ---------------- launch ----------------
extern "C" void kernel_launch(void* const* d_in, const int* in_sizes, int n_in,
                              void* d_out, int out_size) {
    const float* x    = (const float*)d_in[0];   // (48000, 256)
    const float* cb   = (const float*)d_in[1];   // (1024, 256)
    const float* gcb  = (const float*)d_in[2];   // (64,)
    const float* snum = (const float*)d_in[3];   // (1024,)
    const float* gnum = (const float*)d_in[4];   // (64,)

    float* out       = (float*)d_out;
    float* out_q     = out;                             // 12,288,000
    float* out_shape = out_q + (size_t)N_ROWS * DIMS;   // 262,144
    float* out_gain  = out_shape + KCODES * DIMS;       // 64
    float* out_snum  = out_gain + GK;                   // 1024
    float* out_gnum  = out_snum + KCODES;               // 64

    init_kernel<<<(KCODES * DIMS + 255) / 256, 256>>>();
    prep_x<<<NB, 256>>>(x);
    prep_cb<<<128, 256>>>(cb);

    // smem: A 32768 + B 65536 + cand 12288 + misc 768 = 111360 B
    size_t smem = 111360;
    cudaFuncSetAttribute(vq_main, cudaFuncAttributeMaxDynamicSharedMemorySize,
                         (int)smem);
    vq_main<<<NB, 256, smem>>>(x, cb, gcb, out_q);

    vq_finalize<<<KCODES, 256>>>(cb, gcb, snum, gnum,
                                 out_shape, out_gain, out_snum, out_gnum);
}